// round 2
// baseline (speedup 1.0000x reference)
#include <cuda_runtime.h>
#include <cuda_fp16.h>
#include <cstdint>
#include <cstddef>

// ---------------------------------------------------------------------------
// Problem dims
//   x: (2,2048,4096) fp32  -> treat as (M=4096, K=4096)
//   w_gate, w_up: (8, 1366, 512) fp32 ;  w_down: (8, 512, 1366) fp32
//   HIDDEN = 10928 (= 8*1366), N_EMBD = 4096 (= 8*512)
// Effective dense weights (octonion structure folded):
//   Mg,Mu: (10928 x 4096), Md: (4096 x 10928)
// out = silu(x@Mg^T) * (x@Mu^T)  @ Md^T      (all with ternary-dequant weights)
// ---------------------------------------------------------------------------

static constexpr int MROWS   = 4096;        // B*T
static constexpr int KD      = 4096;        // N_EMBD
static constexpr int NH      = 10928;       // HIDDEN
static constexpr int NH_PAD  = 11008;       // 86 * 128 (row padding for B tiles)
static constexpr int K2      = 10944;       // HIDDEN padded to multiple of 32
static constexpr int WN      = 8 * 1366 * 512;   // elements per weight tensor

// ------------------------- device scratch (zero-init) ----------------------
__device__ __half g_Mg[(size_t)NH_PAD * KD];
__device__ __half g_Mu[(size_t)NH_PAD * KD];
__device__ __half g_Md[(size_t)4096 * K2];
__device__ __half g_X [(size_t)MROWS * KD];
__device__ __half g_H [(size_t)MROWS * K2];
__device__ float  g_red[3 * 256];
__device__ float  g_scales[3];

__constant__ int c_tri[7][3] = {{1,2,3},{1,4,5},{1,7,6},{2,4,6},{2,5,7},{3,4,7},{3,6,5}};

// ---------------------------------------------------------------------------
// 1) abs-sum partials (deterministic: fixed per-thread strided order + tree)
// ---------------------------------------------------------------------------
__global__ void reduce_abs_kernel(const float* __restrict__ w0,
                                  const float* __restrict__ w1,
                                  const float* __restrict__ w2, int n) {
    int t = blockIdx.y;
    const float* w = (t == 0) ? w0 : (t == 1 ? w1 : w2);
    float s = 0.f;
    for (int i = blockIdx.x * blockDim.x + threadIdx.x; i < n;
         i += gridDim.x * blockDim.x)
        s += fabsf(w[i]);
    __shared__ float sh[256];
    sh[threadIdx.x] = s;
    __syncthreads();
    for (int st = 128; st > 0; st >>= 1) {
        if (threadIdx.x < st) sh[threadIdx.x] += sh[threadIdx.x + st];
        __syncthreads();
    }
    if (threadIdx.x == 0) g_red[t * 256 + blockIdx.x] = sh[0];
}

__global__ void finalize_scales_kernel(int n) {
    __shared__ float sh[256];
    for (int t = 0; t < 3; t++) {
        sh[threadIdx.x] = g_red[t * 256 + threadIdx.x];
        __syncthreads();
        for (int st = 128; st > 0; st >>= 1) {
            if (threadIdx.x < st) sh[threadIdx.x] += sh[threadIdx.x + st];
            __syncthreads();
        }
        if (threadIdx.x == 0) g_scales[t] = sh[0] / (float)n;
        __syncthreads();
    }
}

// ---------------------------------------------------------------------------
// 2) x fp32 -> fp16
// ---------------------------------------------------------------------------
__global__ void convert_x_kernel(const float4* __restrict__ x, __half2* __restrict__ o,
                                 int n4) {
    int i = blockIdx.x * blockDim.x + threadIdx.x;
    if (i < n4) {
        float4 v = x[i];
        o[2 * i]     = __floats2half2_rn(v.x, v.y);
        o[2 * i + 1] = __floats2half2_rn(v.z, v.w);
    }
}

// ---------------------------------------------------------------------------
// 3) build effective ternary fp16 matrix with octonion structure folded in
//    M[r = k*out8+o, c = i*in8+d] = sgn(i,k) * clip(round(W[j(i,k),o,d]/s),-1,1)
// ---------------------------------------------------------------------------
__device__ __forceinline__ void oct_jsgn(int i, int k, int& j, float& sgn) {
    if (i == 0) { j = k; sgn = 1.f; return; }
    if (k == 0) { j = i; sgn = -1.f; return; }
    if (i == k) { j = 0; sgn = 1.f; return; }
    #pragma unroll
    for (int t = 0; t < 7; t++) {
        int a = c_tri[t][0], b = c_tri[t][1], c = c_tri[t][2];
        bool hi = (i == a || i == b || i == c);
        bool hk = (k == a || k == b || k == c);
        if (hi && hk) {
            j = a + b + c - i - k;
            bool pos = (j == a && i == b && k == c) ||
                       (j == b && i == c && k == a) ||
                       (j == c && i == a && k == b);
            sgn = pos ? 1.f : -1.f;
            return;
        }
    }
    j = 0; sgn = 0.f;  // unreachable
}

__global__ void build_M_kernel(__half* __restrict__ out, int out_ld,
                               const float* __restrict__ W,
                               int out8, int in8, int ncols, int scale_idx) {
    int r = blockIdx.y;
    int c = blockIdx.x * blockDim.x + threadIdx.x;
    if (c >= ncols) return;
    int k = r / out8, o = r % out8;
    int i = c / in8,  d = c % in8;
    int j; float sgn;
    oct_jsgn(i, k, j, sgn);
    float s = g_scales[scale_idx];
    float q = rintf(W[((size_t)j * out8 + o) * in8 + d] / s);
    q = fminf(1.f, fmaxf(-1.f, q)) * sgn;
    out[(size_t)r * out_ld + c] = __float2half_rn(q);
}

// ---------------------------------------------------------------------------
// 4) GEMM: mma.sync m16n8k16 f16->f32, BM=BN=128, BK=32, 256 thr (2x4 warps),
//    cp.async double-buffered.  NB=2: fused gate+up with SiLU epilogue -> fp16
//    NB=1: single GEMM -> fp32 out, scaled.
// ---------------------------------------------------------------------------
__device__ __forceinline__ void cp16(void* smem_ptr, const void* gmem) {
    uint32_t s = (uint32_t)__cvta_generic_to_shared(smem_ptr);
    asm volatile("cp.async.cg.shared.global [%0], [%1], 16;\n" :: "r"(s), "l"(gmem));
}

__device__ __forceinline__ void mma16816(float c[4], const uint32_t a[4],
                                         const uint32_t b[2]) {
    asm("mma.sync.aligned.m16n8k16.row.col.f32.f16.f16.f32 "
        "{%0,%1,%2,%3}, {%4,%5,%6,%7}, {%8,%9}, {%0,%1,%2,%3};\n"
        : "+f"(c[0]), "+f"(c[1]), "+f"(c[2]), "+f"(c[3])
        : "r"(a[0]), "r"(a[1]), "r"(a[2]), "r"(a[3]), "r"(b[0]), "r"(b[1]));
}

template <int NB>
__global__ void __launch_bounds__(256, 1)
gemm_kernel(const __half* __restrict__ A, int lda,
            const __half* __restrict__ B0g, const __half* __restrict__ B1g, int ldb,
            __half* __restrict__ Ch, float* __restrict__ Cf, int ldc,
            int Nvalid, int KT, int scale_base) {
    extern __shared__ __align__(16) __half sm[];
    constexpr int A_T = 128 * 40;
    constexpr int B_T = 128 * 40;
    constexpr int STG = A_T + NB * B_T;

    const int tid  = threadIdx.x;
    const int warp = tid >> 5, lane = tid & 31;
    const int wm = warp >> 2, wn = warp & 3;
    const int m0 = wm * 64, n0 = wn * 32;
    const int grp = lane >> 2, tig = lane & 3;

    const __half* Ag  = A   + (size_t)blockIdx.y * 128 * lda;
    const __half* Bg0 = B0g + (size_t)blockIdx.x * 128 * ldb;
    const __half* Bg1 = (NB == 2) ? (B1g + (size_t)blockIdx.x * 128 * ldb) : nullptr;

    float acc0[4][4][4];
    float acc1[4][4][4];
    #pragma unroll
    for (int a = 0; a < 4; a++)
        #pragma unroll
        for (int b = 0; b < 4; b++)
            #pragma unroll
            for (int e = 0; e < 4; e++) { acc0[a][b][e] = 0.f; acc1[a][b][e] = 0.f; }

    auto do_load = [&](int kt, int s) {
        __half* As  = sm + s * STG;
        __half* Bs0 = As + A_T;
        __half* Bs1 = Bs0 + B_T;
        int k0 = kt * 32;
        #pragma unroll
        for (int i = 0; i < 2; i++) {
            int idx = i * 256 + tid;
            int row = idx >> 2, cc = (idx & 3) * 8;
            cp16(As  + row * 40 + cc, Ag  + (size_t)row * lda + k0 + cc);
            cp16(Bs0 + row * 40 + cc, Bg0 + (size_t)row * ldb + k0 + cc);
            if (NB == 2)
                cp16(Bs1 + row * 40 + cc, Bg1 + (size_t)row * ldb + k0 + cc);
        }
        asm volatile("cp.async.commit_group;\n" ::);
    };

    do_load(0, 0);
    for (int kt = 0; kt < KT; ++kt) {
        int cur = kt & 1;
        bool more = (kt + 1) < KT;
        if (more) do_load(kt + 1, cur ^ 1);
        if (more) asm volatile("cp.async.wait_group 1;\n" ::);
        else      asm volatile("cp.async.wait_group 0;\n" ::);
        __syncthreads();

        const __half* As  = sm + cur * STG;
        const __half* Bs0 = As + A_T;
        const __half* Bs1 = Bs0 + B_T;

        #pragma unroll
        for (int ksid = 0; ksid < 2; ksid++) {
            const int ks = ksid * 16;
            uint32_t af[4][4];
            #pragma unroll
            for (int mi = 0; mi < 4; mi++) {
                int r = m0 + mi * 16 + grp;
                int c = ks + tig * 2;
                af[mi][0] = *(const uint32_t*)(As + r * 40 + c);
                af[mi][1] = *(const uint32_t*)(As + (r + 8) * 40 + c);
                af[mi][2] = *(const uint32_t*)(As + r * 40 + c + 8);
                af[mi][3] = *(const uint32_t*)(As + (r + 8) * 40 + c + 8);
            }
            uint32_t bf0[4][2], bf1[4][2];
            #pragma unroll
            for (int ni = 0; ni < 4; ni++) {
                int rr = n0 + ni * 8 + grp;
                int c = ks + tig * 2;
                bf0[ni][0] = *(const uint32_t*)(Bs0 + rr * 40 + c);
                bf0[ni][1] = *(const uint32_t*)(Bs0 + rr * 40 + c + 8);
                if (NB == 2) {
                    bf1[ni][0] = *(const uint32_t*)(Bs1 + rr * 40 + c);
                    bf1[ni][1] = *(const uint32_t*)(Bs1 + rr * 40 + c + 8);
                }
            }
            #pragma unroll
            for (int mi = 0; mi < 4; mi++)
                #pragma unroll
                for (int ni = 0; ni < 4; ni++) {
                    mma16816(acc0[mi][ni], af[mi], bf0[ni]);
                    if (NB == 2) mma16816(acc1[mi][ni], af[mi], bf1[ni]);
                }
        }
        __syncthreads();
    }

    // epilogue
    const float s0 = g_scales[scale_base];
    const float s1 = (NB == 2) ? g_scales[scale_base + 1] : 0.f;
    #pragma unroll
    for (int mi = 0; mi < 4; mi++) {
        #pragma unroll
        for (int ni = 0; ni < 4; ni++) {
            int rbase = blockIdx.y * 128 + m0 + mi * 16 + grp;
            int cbase = blockIdx.x * 128 + n0 + ni * 8 + tig * 2;
            #pragma unroll
            for (int e = 0; e < 4; e++) {
                int r = rbase + ((e >= 2) ? 8 : 0);
                int c = cbase + (e & 1);
                if (c < Nvalid) {
                    if (NB == 2) {
                        float g = acc0[mi][ni][e] * s0;
                        float u = acc1[mi][ni][e] * s1;
                        float h = u * (g / (1.f + expf(-g)));
                        Ch[(size_t)r * ldc + c] = __float2half_rn(h);
                    } else {
                        Cf[(size_t)r * ldc + c] = acc0[mi][ni][e] * s0;
                    }
                }
            }
        }
    }
}

// ---------------------------------------------------------------------------
// launcher
// ---------------------------------------------------------------------------
extern "C" void kernel_launch(void* const* d_in, const int* in_sizes, int n_in,
                              void* d_out, int out_size) {
    (void)in_sizes; (void)n_in; (void)out_size;
    const float* x  = (const float*)d_in[0];
    const float* wg = (const float*)d_in[1];
    const float* wu = (const float*)d_in[2];
    const float* wd = (const float*)d_in[3];
    float* out = (float*)d_out;

    void* p;
    cudaGetSymbolAddress(&p, g_Mg); __half* Mg = (__half*)p;
    cudaGetSymbolAddress(&p, g_Mu); __half* Mu = (__half*)p;
    cudaGetSymbolAddress(&p, g_Md); __half* Md = (__half*)p;
    cudaGetSymbolAddress(&p, g_X);  __half* X  = (__half*)p;
    cudaGetSymbolAddress(&p, g_H);  __half* Hb = (__half*)p;

    // 1) scales
    reduce_abs_kernel<<<dim3(256, 3), 256>>>(wg, wu, wd, WN);
    finalize_scales_kernel<<<1, 256>>>(WN);

    // 2) x -> fp16
    convert_x_kernel<<<(MROWS * KD / 4) / 256, 256>>>(
        (const float4*)x, (__half2*)X, MROWS * KD / 4);

    // 3) build effective ternary matrices
    build_M_kernel<<<dim3((KD + 255) / 256, NH), 256>>>(Mg, KD, wg, 1366, 512, KD, 0);
    build_M_kernel<<<dim3((KD + 255) / 256, NH), 256>>>(Mu, KD, wu, 1366, 512, KD, 1);
    build_M_kernel<<<dim3((NH + 255) / 256, 4096), 256>>>(Md, K2, wd, 512, 1366, NH, 2);

    // 4) GEMMs
    constexpr int SMEM_FUSED  = 2 * (128 * 40 + 2 * 128 * 40) * (int)sizeof(__half); // 61440
    constexpr int SMEM_SINGLE = 2 * (128 * 40 + 1 * 128 * 40) * (int)sizeof(__half); // 40960
    cudaFuncSetAttribute((const void*)gemm_kernel<2>,
                         cudaFuncAttributeMaxDynamicSharedMemorySize, SMEM_FUSED);
    cudaFuncSetAttribute((const void*)gemm_kernel<1>,
                         cudaFuncAttributeMaxDynamicSharedMemorySize, SMEM_SINGLE);

    // gate+up fused -> H (fp16, ld = K2 padded; pad cols stay zero-init)
    gemm_kernel<2><<<dim3(NH_PAD / 128, MROWS / 128), 256, SMEM_FUSED>>>(
        X, KD, Mg, Mu, KD, Hb, nullptr, K2, NH, KD / 32, 0);

    // down -> out (fp32)
    gemm_kernel<1><<<dim3(4096 / 128, MROWS / 128), 256, SMEM_SINGLE>>>(
        Hb, K2, Md, nullptr, K2, nullptr, out, 4096, 4096, K2 / 32, 2);
}

// round 4
// speedup vs baseline: 1.4150x; 1.4150x over previous
#include <cuda_runtime.h>
#include <cuda_fp16.h>
#include <cstdint>
#include <cstddef>

// ---------------------------------------------------------------------------
// out = silu(x@Mg^T)*(x@Mu^T) @ Md^T, ternary-dequant octonion weights.
// Octonion structure collapses to j = i XOR k + sign LUT (hand-verified).
// tcgen05 unavailable (harness targets plain sm_103) -> optimized mma.sync:
//   BM=128 BN=128 BK=64, 3-stage cp.async, ldmatrix.x4, 1 sync per ktile.
// ---------------------------------------------------------------------------

static constexpr int MROWS = 4096, KD = 4096, NH = 10928, NH_PAD = 11008, K2 = 10944;
static constexpr int WN = 8 * 1366 * 512;

__device__ __half g_Mg[(size_t)NH_PAD * KD];
__device__ __half g_Mu[(size_t)NH_PAD * KD];
__device__ __half g_Md[(size_t)4096 * K2];
__device__ __half g_X [(size_t)MROWS * KD];
__device__ __half g_H [(size_t)MROWS * K2];
__device__ float  g_red[3 * 256];
__device__ float  g_scales[3];

// sign LUT: s[i*8+k] = S[i^k, i, k]  (verified against all Fano triples)
__constant__ float c_S[64] = {
 +1,+1,+1,+1,+1,+1,+1,+1,
 -1,+1,+1,-1,+1,-1,-1,+1,
 -1,-1,+1,+1,+1,+1,-1,-1,
 -1,+1,-1,+1,+1,-1,+1,-1,
 -1,-1,-1,-1,+1,+1,+1,+1,
 -1,+1,-1,+1,-1,+1,-1,+1,
 -1,+1,+1,-1,-1,+1,+1,-1,
 -1,-1,+1,+1,-1,-1,+1,+1};

// ---------------------------------------------------------------------------
// scales (deterministic two-level tree)
// ---------------------------------------------------------------------------
__global__ void reduce_abs_kernel(const float* __restrict__ w0,
                                  const float* __restrict__ w1,
                                  const float* __restrict__ w2, int n) {
    int t = blockIdx.y;
    const float* w = (t == 0) ? w0 : (t == 1 ? w1 : w2);
    float s = 0.f;
    for (int i = blockIdx.x * blockDim.x + threadIdx.x; i < n;
         i += gridDim.x * blockDim.x)
        s += fabsf(w[i]);
    __shared__ float sh[256];
    sh[threadIdx.x] = s;
    __syncthreads();
    for (int st = 128; st > 0; st >>= 1) {
        if (threadIdx.x < st) sh[threadIdx.x] += sh[threadIdx.x + st];
        __syncthreads();
    }
    if (threadIdx.x == 0) g_red[t * 256 + blockIdx.x] = sh[0];
}

__global__ void finalize_scales_kernel(int n) {
    __shared__ float sh[256];
    for (int t = 0; t < 3; t++) {
        sh[threadIdx.x] = g_red[t * 256 + threadIdx.x];
        __syncthreads();
        for (int st = 128; st > 0; st >>= 1) {
            if (threadIdx.x < st) sh[threadIdx.x] += sh[threadIdx.x + st];
            __syncthreads();
        }
        if (threadIdx.x == 0) g_scales[t] = sh[0] / (float)n;
        __syncthreads();
    }
}

__global__ void convert_x_kernel(const float4* __restrict__ x, __half2* __restrict__ o,
                                 int n4) {
    int i = blockIdx.x * blockDim.x + threadIdx.x;
    if (i < n4) {
        float4 v = x[i];
        o[2 * i]     = __floats2half2_rn(v.x, v.y);
        o[2 * i + 1] = __floats2half2_rn(v.z, v.w);
    }
}

// ---------------------------------------------------------------------------
// build effective ternary fp16 matrices (j = i ^ k, sign LUT)
// ---------------------------------------------------------------------------
__global__ void build_gu_kernel(__half* __restrict__ out, const float* __restrict__ W,
                                int si) {
    int r  = blockIdx.y;                             // 0..NH-1
    int c8 = blockIdx.x * blockDim.x + threadIdx.x;  // 0..511
    int c  = c8 * 8;
    int k = r / 1366, o = r - k * 1366;
    int i = c >> 9, d = c & 511;
    int j = i ^ k;
    float sg = c_S[i * 8 + k];
    float s  = g_scales[si];
    const float4* src = (const float4*)(W + ((size_t)(j * 1366 + o)) * 512 + d);
    float4 v0 = src[0], v1 = src[1];
    float q[8] = {v0.x, v0.y, v0.z, v0.w, v1.x, v1.y, v1.z, v1.w};
    __align__(16) __half h[8];
#pragma unroll
    for (int t = 0; t < 8; t++) {
        float qq = rintf(q[t] / s);
        qq = fminf(1.f, fmaxf(-1.f, qq)) * sg;
        h[t] = __float2half_rn(qq);
    }
    *(uint4*)(out + (size_t)r * 4096 + c) = *(uint4*)h;
}

__global__ void build_d_kernel(__half* __restrict__ out, const float* __restrict__ W) {
    int r = blockIdx.y;                              // 0..4095
    int c = blockIdx.x * blockDim.x + threadIdx.x;
    if (c >= NH) return;
    int k = r >> 9, o = r & 511;
    int i = c / 1366, d = c - i * 1366;
    int j = i ^ k;
    float sg = c_S[i * 8 + k];
    float s  = g_scales[2];
    float q = rintf(W[((size_t)(j * 512 + o)) * 1366 + d] / s);
    q = fminf(1.f, fmaxf(-1.f, q)) * sg;
    out[(size_t)r * K2 + c] = __float2half_rn(q);
}

// ---------------------------------------------------------------------------
// GEMM helpers
// ---------------------------------------------------------------------------
__device__ __forceinline__ uint32_t smem_u32(const void* p) {
    return (uint32_t)__cvta_generic_to_shared(p);
}
__device__ __forceinline__ void cp16(uint32_t s, const void* g) {
    asm volatile("cp.async.cg.shared.global [%0], [%1], 16;\n" :: "r"(s), "l"(g));
}
__device__ __forceinline__ void ldsm4(uint32_t& r0, uint32_t& r1, uint32_t& r2,
                                      uint32_t& r3, uint32_t addr) {
    asm volatile("ldmatrix.sync.aligned.m8n8.x4.shared.b16 {%0,%1,%2,%3}, [%4];"
                 : "=r"(r0), "=r"(r1), "=r"(r2), "=r"(r3) : "r"(addr));
}
__device__ __forceinline__ void mma16816(float c[4], const uint32_t a[4],
                                         const uint32_t b[2]) {
    asm("mma.sync.aligned.m16n8k16.row.col.f32.f16.f16.f32 "
        "{%0,%1,%2,%3}, {%4,%5,%6,%7}, {%8,%9}, {%0,%1,%2,%3};\n"
        : "+f"(c[0]), "+f"(c[1]), "+f"(c[2]), "+f"(c[3])
        : "r"(a[0]), "r"(a[1]), "r"(a[2]), "r"(a[3]), "r"(b[0]), "r"(b[1]));
}

// ---------------------------------------------------------------------------
// HMMA GEMM: C(128x128) = A(128xK) * B(128xK)^T  (both K-major)
// NB=2: fused gate+up, SiLU epilogue -> fp16 ; NB=1: fp32 out, scaled
// 3-stage cp.async, BK=64, ldmatrix.x4, padded smem stride 72
// ---------------------------------------------------------------------------
template <int NB>
__global__ void __launch_bounds__(256, 1)
hgemm(const __half* __restrict__ A, int lda,
      const __half* __restrict__ B0g, const __half* __restrict__ B1g, int ldb,
      __half* __restrict__ Ch, float* __restrict__ Cf, int ldc,
      int Nvalid, int KT, int sbase) {
    extern __shared__ __align__(16) __half sm[];
    constexpr int LDA  = 72;                       // halfs; conflict-free ldmatrix
    constexpr int TSZ  = 128 * LDA;                // halfs per tile
    constexpr int STG  = TSZ * (1 + NB);           // halfs per stage

    const int tid  = threadIdx.x;
    const int warp = tid >> 5, lane = tid & 31;
    const int wm = warp >> 2, wn = warp & 3;       // 2x4 warp grid
    const int m0 = wm * 64, n0 = wn * 32;

    const __half* Ag  = A   + (size_t)blockIdx.y * 128 * lda;
    const __half* Bg0 = B0g + (size_t)blockIdx.x * 128 * ldb;
    const __half* Bg1 = (NB == 2) ? (B1g + (size_t)blockIdx.x * 128 * ldb) : nullptr;

    // per-thread ldmatrix base offsets (halfs, within a stage tile)
    int a_row = m0 + (lane & 7) + ((lane >> 3) & 1) * 8;
    int a_col = (lane >> 4) * 8;
    int aoff[4];
#pragma unroll
    for (int mi = 0; mi < 4; mi++) aoff[mi] = (a_row + mi * 16) * LDA + a_col;
    int b_row = n0 + (lane & 7) + ((lane >> 4) & 1) * 8;
    int b_col = ((lane >> 3) & 1) * 8;
    int boff[2];
#pragma unroll
    for (int p = 0; p < 2; p++) boff[p] = (b_row + p * 16) * LDA + b_col;

    const uint32_t sb = smem_u32(sm);

    float acc0[4][4][4];
    float acc1[4][4][4];
#pragma unroll
    for (int a = 0; a < 4; a++)
#pragma unroll
        for (int b = 0; b < 4; b++)
#pragma unroll
            for (int e = 0; e < 4; e++) { acc0[a][b][e] = 0.f; acc1[a][b][e] = 0.f; }

    auto load_tile = [&](int kt, int s) {
        uint32_t st = sb + (uint32_t)(s * STG) * 2;
        int k0 = kt * 64;
#pragma unroll
        for (int u = 0; u < 4; u++) {            // A: 1024 chunks / 256 thr
            int id = u * 256 + tid;
            int row = id >> 3, ch = id & 7;
            cp16(st + row * (LDA * 2) + ch * 16,
                 Ag + (size_t)row * lda + k0 + ch * 8);
        }
#pragma unroll
        for (int u = 0; u < 4; u++) {            // B0
            int id = u * 256 + tid;
            int row = id >> 3, ch = id & 7;
            cp16(st + TSZ * 2 + row * (LDA * 2) + ch * 16,
                 Bg0 + (size_t)row * ldb + k0 + ch * 8);
        }
        if (NB == 2) {
#pragma unroll
            for (int u = 0; u < 4; u++) {        // B1
                int id = u * 256 + tid;
                int row = id >> 3, ch = id & 7;
                cp16(st + TSZ * 4 + row * (LDA * 2) + ch * 16,
                     Bg1 + (size_t)row * ldb + k0 + ch * 8);
            }
        }
        asm volatile("cp.async.commit_group;" ::: "memory");
    };

    load_tile(0, 0);
    load_tile(1, 1);

    int stage = 0;
    for (int kt = 0; kt < KT; kt++) {
        if (kt + 1 < KT) asm volatile("cp.async.wait_group 1;" ::: "memory");
        else             asm volatile("cp.async.wait_group 0;" ::: "memory");
        __syncthreads();     // also guards overwrite of stage (kt+2)%3 below

        if (kt + 2 < KT) {
            int ns = stage + 2; if (ns >= 3) ns -= 3;
            load_tile(kt + 2, ns);
        }

        uint32_t ab = sb + (uint32_t)(stage * STG) * 2;
        uint32_t bb0 = ab + TSZ * 2;
        uint32_t bb1 = ab + TSZ * 4;

#pragma unroll
        for (int ksid = 0; ksid < 4; ksid++) {
            const int ks = ksid * 16;
            uint32_t af[4][4];
#pragma unroll
            for (int mi = 0; mi < 4; mi++)
                ldsm4(af[mi][0], af[mi][1], af[mi][2], af[mi][3],
                      ab + (uint32_t)(aoff[mi] + ks) * 2);
            uint32_t bf0[4][2], bf1[4][2];
#pragma unroll
            for (int p = 0; p < 2; p++)
                ldsm4(bf0[2 * p][0], bf0[2 * p][1], bf0[2 * p + 1][0], bf0[2 * p + 1][1],
                      bb0 + (uint32_t)(boff[p] + ks) * 2);
            if (NB == 2) {
#pragma unroll
                for (int p = 0; p < 2; p++)
                    ldsm4(bf1[2 * p][0], bf1[2 * p][1], bf1[2 * p + 1][0], bf1[2 * p + 1][1],
                          bb1 + (uint32_t)(boff[p] + ks) * 2);
            }
#pragma unroll
            for (int mi = 0; mi < 4; mi++)
#pragma unroll
                for (int ni = 0; ni < 4; ni++) {
                    mma16816(acc0[mi][ni], af[mi], bf0[ni]);
                    if (NB == 2) mma16816(acc1[mi][ni], af[mi], bf1[ni]);
                }
        }
        stage++; if (stage >= 3) stage = 0;
    }

    // epilogue
    const float s0 = g_scales[sbase];
    const float s1 = (NB == 2) ? g_scales[sbase + 1] : 0.f;
    const int grp = lane >> 2, tig = lane & 3;
#pragma unroll
    for (int mi = 0; mi < 4; mi++) {
#pragma unroll
        for (int ni = 0; ni < 4; ni++) {
            int rbase = blockIdx.y * 128 + m0 + mi * 16 + grp;
            int cbase = blockIdx.x * 128 + n0 + ni * 8 + tig * 2;
#pragma unroll
            for (int e = 0; e < 4; e++) {
                int r = rbase + ((e >= 2) ? 8 : 0);
                int c = cbase + (e & 1);
                if (c < Nvalid) {
                    if (NB == 2) {
                        float g = acc0[mi][ni][e] * s0;
                        float u = acc1[mi][ni][e] * s1;
                        float h = u * (g / (1.f + expf(-g)));
                        Ch[(size_t)r * ldc + c] = __float2half_rn(h);
                    } else {
                        Cf[(size_t)r * ldc + c] = acc0[mi][ni][e] * s0;
                    }
                }
            }
        }
    }
}

// ---------------------------------------------------------------------------
// launcher
// ---------------------------------------------------------------------------
extern "C" void kernel_launch(void* const* d_in, const int* in_sizes, int n_in,
                              void* d_out, int out_size) {
    (void)in_sizes; (void)n_in; (void)out_size;
    const float* x  = (const float*)d_in[0];
    const float* wg = (const float*)d_in[1];
    const float* wu = (const float*)d_in[2];
    const float* wd = (const float*)d_in[3];
    float* out = (float*)d_out;

    void* p;
    cudaGetSymbolAddress(&p, g_Mg); __half* Mg = (__half*)p;
    cudaGetSymbolAddress(&p, g_Mu); __half* Mu = (__half*)p;
    cudaGetSymbolAddress(&p, g_Md); __half* Md = (__half*)p;
    cudaGetSymbolAddress(&p, g_X);  __half* X  = (__half*)p;
    cudaGetSymbolAddress(&p, g_H);  __half* Hb = (__half*)p;

    reduce_abs_kernel<<<dim3(256, 3), 256>>>(wg, wu, wd, WN);
    finalize_scales_kernel<<<1, 256>>>(WN);

    convert_x_kernel<<<(MROWS * KD / 4) / 256, 256>>>(
        (const float4*)x, (__half2*)X, MROWS * KD / 4);

    build_gu_kernel<<<dim3(2, NH), 256>>>(Mg, wg, 0);
    build_gu_kernel<<<dim3(2, NH), 256>>>(Mu, wu, 1);
    build_d_kernel<<<dim3((NH + 255) / 256, 4096), 256>>>(Md, wd);

    constexpr int SMEM2 = 3 * (128 * 72 * 3) * (int)sizeof(__half);  // 165888
    constexpr int SMEM1 = 3 * (128 * 72 * 2) * (int)sizeof(__half);  // 110592
    cudaFuncSetAttribute((const void*)hgemm<2>,
                         cudaFuncAttributeMaxDynamicSharedMemorySize, SMEM2);
    cudaFuncSetAttribute((const void*)hgemm<1>,
                         cudaFuncAttributeMaxDynamicSharedMemorySize, SMEM1);

    // fused gate+up -> H (fp16); pad cols [NH,K2) of H stay zero-init
    hgemm<2><<<dim3(NH_PAD / 128, MROWS / 128), 256, SMEM2>>>(
        X, KD, Mg, Mu, KD, Hb, nullptr, K2, NH, KD / 64, 0);

    // down -> out (fp32); Md pad cols [NH,K2) are zero
    hgemm<1><<<dim3(4096 / 128, MROWS / 128), 256, SMEM1>>>(
        Hb, K2, Md, nullptr, K2, nullptr, out, 4096, 4096, K2 / 64, 2);
}

// round 6
// speedup vs baseline: 1.4474x; 1.0229x over previous
#include <cuda_runtime.h>
#include <cuda_fp16.h>
#include <cstdint>
#include <cstddef>

// ---------------------------------------------------------------------------
// out = silu(x@Mg^T)*(x@Mu^T) @ Md^T, ternary-dequant octonion weights.
// Octonion structure collapses to j = i XOR k + sign LUT.
// mma.sync HMMA path (tcgen05 rejected by harness's plain sm_103 ptxas target).
//   Both GEMMs: BM=128, dual-B NB=2 mainloop, BK=64, 3-stage cp.async,
//   ldmatrix.x4, vectorized epilogues.
// ---------------------------------------------------------------------------

static constexpr int MROWS = 4096, KD = 4096, NH = 10928, NH_PAD = 11008, K2 = 10944;
static constexpr int WN = 8 * 1366 * 512;

__device__ __half g_Mg[(size_t)NH_PAD * KD];
__device__ __half g_Mu[(size_t)NH_PAD * KD];
__device__ __half g_Md[(size_t)4096 * K2];
__device__ __half g_X [(size_t)MROWS * KD];
__device__ __half g_H [(size_t)MROWS * K2];
__device__ float  g_red[3 * 256];
__device__ float  g_scales[3];

// sign LUT: s[i*8+k] = S[i^k, i, k]
__constant__ float c_S[64] = {
 +1,+1,+1,+1,+1,+1,+1,+1,
 -1,+1,+1,-1,+1,-1,-1,+1,
 -1,-1,+1,+1,+1,+1,-1,-1,
 -1,+1,-1,+1,+1,-1,+1,-1,
 -1,-1,-1,-1,+1,+1,+1,+1,
 -1,+1,-1,+1,-1,+1,-1,+1,
 -1,+1,+1,-1,-1,+1,+1,-1,
 -1,-1,+1,+1,-1,-1,+1,+1};

// ---------------------------------------------------------------------------
// scales (deterministic two-level tree)
// ---------------------------------------------------------------------------
__global__ void reduce_abs_kernel(const float* __restrict__ w0,
                                  const float* __restrict__ w1,
                                  const float* __restrict__ w2, int n) {
    int t = blockIdx.y;
    const float* w = (t == 0) ? w0 : (t == 1 ? w1 : w2);
    float s = 0.f;
    for (int i = blockIdx.x * blockDim.x + threadIdx.x; i < n;
         i += gridDim.x * blockDim.x)
        s += fabsf(w[i]);
    __shared__ float sh[256];
    sh[threadIdx.x] = s;
    __syncthreads();
    for (int st = 128; st > 0; st >>= 1) {
        if (threadIdx.x < st) sh[threadIdx.x] += sh[threadIdx.x + st];
        __syncthreads();
    }
    if (threadIdx.x == 0) g_red[t * 256 + blockIdx.x] = sh[0];
}

__global__ void finalize_scales_kernel(int n) {
    __shared__ float sh[256];
    for (int t = 0; t < 3; t++) {
        sh[threadIdx.x] = g_red[t * 256 + threadIdx.x];
        __syncthreads();
        for (int st = 128; st > 0; st >>= 1) {
            if (threadIdx.x < st) sh[threadIdx.x] += sh[threadIdx.x + st];
            __syncthreads();
        }
        if (threadIdx.x == 0) g_scales[t] = sh[0] / (float)n;
        __syncthreads();
    }
}

__global__ void convert_x_kernel(const float4* __restrict__ x, __half2* __restrict__ o,
                                 int n4) {
    int i = blockIdx.x * blockDim.x + threadIdx.x;
    if (i < n4) {
        float4 v = x[i];
        o[2 * i]     = __floats2half2_rn(v.x, v.y);
        o[2 * i + 1] = __floats2half2_rn(v.z, v.w);
    }
}

// ---------------------------------------------------------------------------
// merged build: one launch fills Mg, Mu, Md  (j = i ^ k, sign LUT)
// ---------------------------------------------------------------------------
static constexpr int GU_ITEMS = NH * 512;        // 8-wide items per gu matrix
static constexpr int D_ITEMS  = 4096 * (K2 / 8); // 8-wide items for Md (padded)

__global__ void build_all_kernel(__half* __restrict__ Mg, __half* __restrict__ Mu,
                                 __half* __restrict__ Md,
                                 const float* __restrict__ wg,
                                 const float* __restrict__ wu,
                                 const float* __restrict__ wd) {
    int id = blockIdx.x * blockDim.x + threadIdx.x;
    if (id < 2 * GU_ITEMS) {
        const float* W = (id < GU_ITEMS) ? wg : wu;
        __half* out    = (id < GU_ITEMS) ? Mg : Mu;
        float s        = (id < GU_ITEMS) ? g_scales[0] : g_scales[1];
        int t  = (id < GU_ITEMS) ? id : id - GU_ITEMS;
        int r  = t >> 9;                 // 0..NH-1
        int c  = (t & 511) * 8;
        int k = r / 1366, o = r - k * 1366;
        int i = c >> 9, d = c & 511;
        int j = i ^ k;
        float sg = c_S[i * 8 + k];
        const float4* src = (const float4*)(W + ((size_t)(j * 1366 + o)) * 512 + d);
        float4 v0 = src[0], v1 = src[1];
        float q[8] = {v0.x, v0.y, v0.z, v0.w, v1.x, v1.y, v1.z, v1.w};
        __align__(16) __half h[8];
#pragma unroll
        for (int tt = 0; tt < 8; tt++) {
            float qq = rintf(q[tt] / s);
            qq = fminf(1.f, fmaxf(-1.f, qq)) * sg;
            h[tt] = __float2half_rn(qq);
        }
        *(uint4*)(out + (size_t)r * 4096 + c) = *(uint4*)h;
        return;
    }
    int t = id - 2 * GU_ITEMS;
    if (t >= D_ITEMS) return;
    int r = t / (K2 / 8);                // 0..4095
    int c = (t - r * (K2 / 8)) * 8;
    int k = r >> 9, o = r & 511;
    float s = g_scales[2];
    __align__(16) __half h[8];
#pragma unroll
    for (int tt = 0; tt < 8; tt++) {
        int cc = c + tt;
        if (cc < NH) {
            int i = cc / 1366, d = cc - i * 1366;
            int j = i ^ k;
            float sg = c_S[i * 8 + k];
            float q = rintf(wd[((size_t)(j * 512 + o)) * 1366 + d] / s);
            h[tt] = __float2half_rn(fminf(1.f, fmaxf(-1.f, q)) * sg);
        } else {
            h[tt] = __float2half_rn(0.f);
        }
    }
    *(uint4*)(Md + (size_t)r * K2 + c) = *(uint4*)h;
}

// ---------------------------------------------------------------------------
// GEMM helpers
// ---------------------------------------------------------------------------
__device__ __forceinline__ uint32_t smem_u32(const void* p) {
    return (uint32_t)__cvta_generic_to_shared(p);
}
__device__ __forceinline__ void cp16(uint32_t s, const void* g) {
    asm volatile("cp.async.cg.shared.global [%0], [%1], 16;\n" :: "r"(s), "l"(g));
}
__device__ __forceinline__ void ldsm4(uint32_t& r0, uint32_t& r1, uint32_t& r2,
                                      uint32_t& r3, uint32_t addr) {
    asm volatile("ldmatrix.sync.aligned.m8n8.x4.shared.b16 {%0,%1,%2,%3}, [%4];"
                 : "=r"(r0), "=r"(r1), "=r"(r2), "=r"(r3) : "r"(addr));
}
__device__ __forceinline__ void mma16816(float c[4], const uint32_t a[4],
                                         const uint32_t b[2]) {
    asm("mma.sync.aligned.m16n8k16.row.col.f32.f16.f16.f32 "
        "{%0,%1,%2,%3}, {%4,%5,%6,%7}, {%8,%9}, {%0,%1,%2,%3};\n"
        : "+f"(c[0]), "+f"(c[1]), "+f"(c[2]), "+f"(c[3])
        : "r"(a[0]), "r"(a[1]), "r"(a[2]), "r"(a[3]), "r"(b[0]), "r"(b[1]));
}

// ---------------------------------------------------------------------------
// Dual-B HMMA GEMM: per CTA, A(128xK) against B0,B1 (128xK each), K-major.
// EPI=0 (fused gate+up): B0=gate strip, B1=up strip -> silu(g)*u -> fp16 H
// EPI=1 (down two-strip): B0,B1 = adjacent 128-col strips of Md -> fp32 out
// 3-stage cp.async, BK=64, ldmatrix.x4, padded smem stride 72.
// ---------------------------------------------------------------------------
template <int EPI>
__global__ void __launch_bounds__(256, 1)
hgemm(const __half* __restrict__ A, int lda,
      const __half* __restrict__ Bbase, int ldb,
      __half* __restrict__ Ch, float* __restrict__ Cf, int ldc,
      int Nvalid, int KT, int sbase, int b1_stride_rows,
      const __half* __restrict__ B1base) {
    extern __shared__ __align__(16) __half sm[];
    constexpr int LDA  = 72;
    constexpr int TSZ  = 128 * LDA;
    constexpr int STG  = TSZ * 3;

    const int tid  = threadIdx.x;
    const int warp = tid >> 5, lane = tid & 31;
    const int wm = warp >> 2, wn = warp & 3;
    const int m0 = wm * 64, n0 = wn * 32;

    const __half* Ag = A + (size_t)blockIdx.y * 128 * lda;
    const __half* Bg0;
    const __half* Bg1;
    if (EPI == 0) {
        Bg0 = Bbase  + (size_t)blockIdx.x * 128 * ldb;
        Bg1 = B1base + (size_t)blockIdx.x * 128 * ldb;
    } else {
        Bg0 = Bbase + (size_t)blockIdx.x * b1_stride_rows * ldb;
        Bg1 = Bg0 + (size_t)128 * ldb;
    }

    int a_row = m0 + (lane & 7) + ((lane >> 3) & 1) * 8;
    int a_col = (lane >> 4) * 8;
    int aoff[4];
#pragma unroll
    for (int mi = 0; mi < 4; mi++) aoff[mi] = (a_row + mi * 16) * LDA + a_col;
    int b_row = n0 + (lane & 7) + ((lane >> 4) & 1) * 8;
    int b_col = ((lane >> 3) & 1) * 8;
    int boff[2];
#pragma unroll
    for (int p = 0; p < 2; p++) boff[p] = (b_row + p * 16) * LDA + b_col;

    const uint32_t sb = smem_u32(sm);

    float acc0[4][4][4];
    float acc1[4][4][4];
#pragma unroll
    for (int a = 0; a < 4; a++)
#pragma unroll
        for (int b = 0; b < 4; b++)
#pragma unroll
            for (int e = 0; e < 4; e++) { acc0[a][b][e] = 0.f; acc1[a][b][e] = 0.f; }

    auto load_tile = [&](int kt, int s) {
        uint32_t st = sb + (uint32_t)(s * STG) * 2;
        int k0 = kt * 64;
#pragma unroll
        for (int u = 0; u < 4; u++) {
            int id = u * 256 + tid;
            int row = id >> 3, ch = id & 7;
            cp16(st + row * (LDA * 2) + ch * 16,
                 Ag + (size_t)row * lda + k0 + ch * 8);
        }
#pragma unroll
        for (int u = 0; u < 4; u++) {
            int id = u * 256 + tid;
            int row = id >> 3, ch = id & 7;
            cp16(st + TSZ * 2 + row * (LDA * 2) + ch * 16,
                 Bg0 + (size_t)row * ldb + k0 + ch * 8);
        }
#pragma unroll
        for (int u = 0; u < 4; u++) {
            int id = u * 256 + tid;
            int row = id >> 3, ch = id & 7;
            cp16(st + TSZ * 4 + row * (LDA * 2) + ch * 16,
                 Bg1 + (size_t)row * ldb + k0 + ch * 8);
        }
        asm volatile("cp.async.commit_group;" ::: "memory");
    };

    load_tile(0, 0);
    load_tile(1, 1);

    int stage = 0;
    for (int kt = 0; kt < KT; kt++) {
        if (kt + 1 < KT) asm volatile("cp.async.wait_group 1;" ::: "memory");
        else             asm volatile("cp.async.wait_group 0;" ::: "memory");
        __syncthreads();

        if (kt + 2 < KT) {
            int ns = stage + 2; if (ns >= 3) ns -= 3;
            load_tile(kt + 2, ns);
        }

        uint32_t ab  = sb + (uint32_t)(stage * STG) * 2;
        uint32_t bb0 = ab + TSZ * 2;
        uint32_t bb1 = ab + TSZ * 4;

#pragma unroll
        for (int ksid = 0; ksid < 4; ksid++) {
            const int ks = ksid * 16;
            uint32_t af[4][4];
#pragma unroll
            for (int mi = 0; mi < 4; mi++)
                ldsm4(af[mi][0], af[mi][1], af[mi][2], af[mi][3],
                      ab + (uint32_t)(aoff[mi] + ks) * 2);
            uint32_t bf0[4][2], bf1[4][2];
#pragma unroll
            for (int p = 0; p < 2; p++)
                ldsm4(bf0[2 * p][0], bf0[2 * p][1], bf0[2 * p + 1][0], bf0[2 * p + 1][1],
                      bb0 + (uint32_t)(boff[p] + ks) * 2);
#pragma unroll
            for (int p = 0; p < 2; p++)
                ldsm4(bf1[2 * p][0], bf1[2 * p][1], bf1[2 * p + 1][0], bf1[2 * p + 1][1],
                      bb1 + (uint32_t)(boff[p] + ks) * 2);
#pragma unroll
            for (int mi = 0; mi < 4; mi++)
#pragma unroll
                for (int ni = 0; ni < 4; ni++) {
                    mma16816(acc0[mi][ni], af[mi], bf0[ni]);
                    mma16816(acc1[mi][ni], af[mi], bf1[ni]);
                }
        }
        stage++; if (stage >= 3) stage = 0;
    }

    // epilogue
    const float s0 = g_scales[sbase];
    const float s1 = (EPI == 0) ? g_scales[sbase + 1] : s0;
    const int grp = lane >> 2, tig = lane & 3;

    if constexpr (EPI == 0) {
        const bool edge = ((blockIdx.x + 1) * 128 > (unsigned)Nvalid);
#pragma unroll
        for (int mi = 0; mi < 4; mi++) {
#pragma unroll
            for (int ni = 0; ni < 4; ni++) {
                int rbase = blockIdx.y * 128 + m0 + mi * 16 + grp;
                int cb    = blockIdx.x * 128 + n0 + ni * 8 + tig * 2;
#pragma unroll
                for (int half_e = 0; half_e < 2; half_e++) {   // e={0,1},{2,3}
                    int r = rbase + half_e * 8;
                    float g = acc0[mi][ni][half_e * 2 + 0] * s0;
                    float u = acc1[mi][ni][half_e * 2 + 0] * s1;
                    float h0 = u * (g / (1.f + expf(-g)));
                    g = acc0[mi][ni][half_e * 2 + 1] * s0;
                    u = acc1[mi][ni][half_e * 2 + 1] * s1;
                    float h1 = u * (g / (1.f + expf(-g)));
                    if (!edge || cb < Nvalid)
                        *(__half2*)(Ch + (size_t)r * ldc + cb) =
                            __floats2half2_rn(h0, h1);
                }
            }
        }
    } else {
#pragma unroll
        for (int mi = 0; mi < 4; mi++) {
#pragma unroll
            for (int ni = 0; ni < 4; ni++) {
                int rbase = blockIdx.y * 128 + m0 + mi * 16 + grp;
                int cb0   = blockIdx.x * 256 + n0 + ni * 8 + tig * 2;
#pragma unroll
                for (int half_e = 0; half_e < 2; half_e++) {
                    int r = rbase + half_e * 8;
                    float2 v0, v1;
                    v0.x = acc0[mi][ni][half_e * 2 + 0] * s0;
                    v0.y = acc0[mi][ni][half_e * 2 + 1] * s0;
                    v1.x = acc1[mi][ni][half_e * 2 + 0] * s0;
                    v1.y = acc1[mi][ni][half_e * 2 + 1] * s0;
                    *(float2*)(Cf + (size_t)r * ldc + cb0)       = v0;
                    *(float2*)(Cf + (size_t)r * ldc + cb0 + 128) = v1;
                }
            }
        }
    }
}

// ---------------------------------------------------------------------------
// launcher
// ---------------------------------------------------------------------------
extern "C" void kernel_launch(void* const* d_in, const int* in_sizes, int n_in,
                              void* d_out, int out_size) {
    (void)in_sizes; (void)n_in; (void)out_size;
    const float* x  = (const float*)d_in[0];
    const float* wg = (const float*)d_in[1];
    const float* wu = (const float*)d_in[2];
    const float* wd = (const float*)d_in[3];
    float* out = (float*)d_out;

    void* p;
    cudaGetSymbolAddress(&p, g_Mg); __half* Mg = (__half*)p;
    cudaGetSymbolAddress(&p, g_Mu); __half* Mu = (__half*)p;
    cudaGetSymbolAddress(&p, g_Md); __half* Md = (__half*)p;
    cudaGetSymbolAddress(&p, g_X);  __half* X  = (__half*)p;
    cudaGetSymbolAddress(&p, g_H);  __half* Hb = (__half*)p;

    reduce_abs_kernel<<<dim3(256, 3), 256>>>(wg, wu, wd, WN);          // launch 1
    finalize_scales_kernel<<<1, 256>>>(WN);                            // launch 2

    convert_x_kernel<<<(MROWS * KD / 4) / 256, 256>>>(                 // launch 3
        (const float4*)x, (__half2*)X, MROWS * KD / 4);

    int total_items = 2 * GU_ITEMS + D_ITEMS;
    build_all_kernel<<<(total_items + 255) / 256, 256>>>(              // launch 4
        Mg, Mu, Md, wg, wu, wd);

    constexpr int SMEM = 3 * (128 * 72 * 3) * (int)sizeof(__half);     // 165888
    cudaFuncSetAttribute((const void*)hgemm<0>,
                         cudaFuncAttributeMaxDynamicSharedMemorySize, SMEM);
    cudaFuncSetAttribute((const void*)hgemm<1>,
                         cudaFuncAttributeMaxDynamicSharedMemorySize, SMEM);

    // fused gate+up -> H (fp16)                                       // launch 5
    hgemm<0><<<dim3(NH_PAD / 128, MROWS / 128), 256, SMEM>>>(
        X, KD, Mg, KD, Hb, nullptr, K2, NH, KD / 64, 0, 0, Mu);

    // down two-strip -> out (fp32)                                    // launch 6
    hgemm<1><<<dim3(4096 / 256, MROWS / 128), 256, SMEM>>>(
        Hb, K2, Md, K2, nullptr, out, 4096, 4096, K2 / 64, 2, 256, nullptr);
}

// round 7
// speedup vs baseline: 1.4516x; 1.0029x over previous
#include <cuda_runtime.h>
#include <cuda_fp16.h>
#include <cstdint>
#include <cstddef>

// ---------------------------------------------------------------------------
// out = silu(x@Mg^T)*(x@Mu^T) @ Md^T, ternary-dequant octonion weights.
// Octonion structure collapses to j = i XOR k + sign LUT.
// mma.sync HMMA path (tcgen05 rejected by harness's plain sm_103 target).
// R7: register-fragment ping-pong in the GEMM mainloop (hide LDSM latency),
//     __expf SiLU, convert_x merged into build_all.
// ---------------------------------------------------------------------------

static constexpr int MROWS = 4096, KD = 4096, NH = 10928, NH_PAD = 11008, K2 = 10944;
static constexpr int WN = 8 * 1366 * 512;

__device__ __half g_Mg[(size_t)NH_PAD * KD];
__device__ __half g_Mu[(size_t)NH_PAD * KD];
__device__ __half g_Md[(size_t)4096 * K2];
__device__ __half g_X [(size_t)MROWS * KD];
__device__ __half g_H [(size_t)MROWS * K2];
__device__ float  g_red[3 * 256];
__device__ float  g_scales[3];

// sign LUT: s[i*8+k] = S[i^k, i, k]
__constant__ float c_S[64] = {
 +1,+1,+1,+1,+1,+1,+1,+1,
 -1,+1,+1,-1,+1,-1,-1,+1,
 -1,-1,+1,+1,+1,+1,-1,-1,
 -1,+1,-1,+1,+1,-1,+1,-1,
 -1,-1,-1,-1,+1,+1,+1,+1,
 -1,+1,-1,+1,-1,+1,-1,+1,
 -1,+1,+1,-1,-1,+1,+1,-1,
 -1,-1,+1,+1,-1,-1,+1,+1};

// ---------------------------------------------------------------------------
// scales (deterministic two-level tree)
// ---------------------------------------------------------------------------
__global__ void reduce_abs_kernel(const float* __restrict__ w0,
                                  const float* __restrict__ w1,
                                  const float* __restrict__ w2, int n) {
    int t = blockIdx.y;
    const float* w = (t == 0) ? w0 : (t == 1 ? w1 : w2);
    float s = 0.f;
    for (int i = blockIdx.x * blockDim.x + threadIdx.x; i < n;
         i += gridDim.x * blockDim.x)
        s += fabsf(w[i]);
    __shared__ float sh[256];
    sh[threadIdx.x] = s;
    __syncthreads();
    for (int st = 128; st > 0; st >>= 1) {
        if (threadIdx.x < st) sh[threadIdx.x] += sh[threadIdx.x + st];
        __syncthreads();
    }
    if (threadIdx.x == 0) g_red[t * 256 + blockIdx.x] = sh[0];
}

__global__ void finalize_scales_kernel(int n) {
    __shared__ float sh[256];
    for (int t = 0; t < 3; t++) {
        sh[threadIdx.x] = g_red[t * 256 + threadIdx.x];
        __syncthreads();
        for (int st = 128; st > 0; st >>= 1) {
            if (threadIdx.x < st) sh[threadIdx.x] += sh[threadIdx.x + st];
            __syncthreads();
        }
        if (threadIdx.x == 0) g_scales[t] = sh[0] / (float)n;
        __syncthreads();
    }
}

// ---------------------------------------------------------------------------
// merged build: one launch fills Mg, Mu, Md and converts x -> fp16
// ---------------------------------------------------------------------------
static constexpr int GU_ITEMS = NH * 512;          // 8-wide items per gu matrix
static constexpr int D_ITEMS  = 4096 * (K2 / 8);   // 8-wide items for Md (padded)
static constexpr int X_ITEMS  = MROWS * KD / 8;    // 8-wide items for x convert

__global__ void build_all_kernel(__half* __restrict__ Mg, __half* __restrict__ Mu,
                                 __half* __restrict__ Md, __half* __restrict__ X,
                                 const float* __restrict__ wg,
                                 const float* __restrict__ wu,
                                 const float* __restrict__ wd,
                                 const float* __restrict__ x) {
    int id = blockIdx.x * blockDim.x + threadIdx.x;
    if (id < 2 * GU_ITEMS) {
        const float* W = (id < GU_ITEMS) ? wg : wu;
        __half* out    = (id < GU_ITEMS) ? Mg : Mu;
        float s        = (id < GU_ITEMS) ? g_scales[0] : g_scales[1];
        int t  = (id < GU_ITEMS) ? id : id - GU_ITEMS;
        int r  = t >> 9;                 // 0..NH-1
        int c  = (t & 511) * 8;
        int k = r / 1366, o = r - k * 1366;
        int i = c >> 9, d = c & 511;
        int j = i ^ k;
        float sg = c_S[i * 8 + k];
        const float4* src = (const float4*)(W + ((size_t)(j * 1366 + o)) * 512 + d);
        float4 v0 = src[0], v1 = src[1];
        float q[8] = {v0.x, v0.y, v0.z, v0.w, v1.x, v1.y, v1.z, v1.w};
        __align__(16) __half h[8];
#pragma unroll
        for (int tt = 0; tt < 8; tt++) {
            float qq = rintf(q[tt] / s);
            qq = fminf(1.f, fmaxf(-1.f, qq)) * sg;
            h[tt] = __float2half_rn(qq);
        }
        *(uint4*)(out + (size_t)r * 4096 + c) = *(uint4*)h;
        return;
    }
    int t = id - 2 * GU_ITEMS;
    if (t < D_ITEMS) {
        int r = t / (K2 / 8);            // 0..4095
        int c = (t - r * (K2 / 8)) * 8;
        int k = r >> 9, o = r & 511;
        float s = g_scales[2];
        __align__(16) __half h[8];
#pragma unroll
        for (int tt = 0; tt < 8; tt++) {
            int cc = c + tt;
            if (cc < NH) {
                int i = cc / 1366, d = cc - i * 1366;
                int j = i ^ k;
                float sg = c_S[i * 8 + k];
                float q = rintf(wd[((size_t)(j * 512 + o)) * 1366 + d] / s);
                h[tt] = __float2half_rn(fminf(1.f, fmaxf(-1.f, q)) * sg);
            } else {
                h[tt] = __float2half_rn(0.f);
            }
        }
        *(uint4*)(Md + (size_t)r * K2 + c) = *(uint4*)h;
        return;
    }
    t -= D_ITEMS;
    if (t >= X_ITEMS) return;
    const float4* src = (const float4*)(x + (size_t)t * 8);
    float4 v0 = src[0], v1 = src[1];
    __align__(16) __half h[8];
    *(__half2*)(h + 0) = __floats2half2_rn(v0.x, v0.y);
    *(__half2*)(h + 2) = __floats2half2_rn(v0.z, v0.w);
    *(__half2*)(h + 4) = __floats2half2_rn(v1.x, v1.y);
    *(__half2*)(h + 6) = __floats2half2_rn(v1.z, v1.w);
    *(uint4*)(X + (size_t)t * 8) = *(uint4*)h;
}

// ---------------------------------------------------------------------------
// GEMM helpers
// ---------------------------------------------------------------------------
__device__ __forceinline__ uint32_t smem_u32(const void* p) {
    return (uint32_t)__cvta_generic_to_shared(p);
}
__device__ __forceinline__ void cp16(uint32_t s, const void* g) {
    asm volatile("cp.async.cg.shared.global [%0], [%1], 16;\n" :: "r"(s), "l"(g));
}
__device__ __forceinline__ void ldsm4(uint32_t& r0, uint32_t& r1, uint32_t& r2,
                                      uint32_t& r3, uint32_t addr) {
    asm volatile("ldmatrix.sync.aligned.m8n8.x4.shared.b16 {%0,%1,%2,%3}, [%4];"
                 : "=r"(r0), "=r"(r1), "=r"(r2), "=r"(r3) : "r"(addr));
}
__device__ __forceinline__ void mma16816(float c[4], const uint32_t a[4],
                                         const uint32_t b[2]) {
    asm("mma.sync.aligned.m16n8k16.row.col.f32.f16.f16.f32 "
        "{%0,%1,%2,%3}, {%4,%5,%6,%7}, {%8,%9}, {%0,%1,%2,%3};\n"
        : "+f"(c[0]), "+f"(c[1]), "+f"(c[2]), "+f"(c[3])
        : "r"(a[0]), "r"(a[1]), "r"(a[2]), "r"(a[3]), "r"(b[0]), "r"(b[1]));
}

// ---------------------------------------------------------------------------
// Dual-B HMMA GEMM with register-fragment ping-pong.
// EPI=0 (fused gate+up): B0=gate strip, B1=up strip -> silu(g)*u -> fp16 H
// EPI=1 (down two-strip): B0,B1 = adjacent 128-col strips of Md -> fp32 out
// 3-stage cp.async, BK=64, ldmatrix.x4, padded smem stride 72.
// ---------------------------------------------------------------------------
template <int EPI>
__global__ void __launch_bounds__(256, 1)
hgemm(const __half* __restrict__ A, int lda,
      const __half* __restrict__ Bbase, int ldb,
      __half* __restrict__ Ch, float* __restrict__ Cf, int ldc,
      int Nvalid, int KT, int sbase, int b1_stride_rows,
      const __half* __restrict__ B1base) {
    extern __shared__ __align__(16) __half sm[];
    constexpr int LDA  = 72;
    constexpr int TSZ  = 128 * LDA;
    constexpr int STG  = TSZ * 3;

    const int tid  = threadIdx.x;
    const int warp = tid >> 5, lane = tid & 31;
    const int wm = warp >> 2, wn = warp & 3;
    const int m0 = wm * 64, n0 = wn * 32;

    const __half* Ag = A + (size_t)blockIdx.y * 128 * lda;
    const __half* Bg0;
    const __half* Bg1;
    if (EPI == 0) {
        Bg0 = Bbase  + (size_t)blockIdx.x * 128 * ldb;
        Bg1 = B1base + (size_t)blockIdx.x * 128 * ldb;
    } else {
        Bg0 = Bbase + (size_t)blockIdx.x * b1_stride_rows * ldb;
        Bg1 = Bg0 + (size_t)128 * ldb;
    }

    int a_row = m0 + (lane & 7) + ((lane >> 3) & 1) * 8;
    int a_col = (lane >> 4) * 8;
    int aoff[4];
#pragma unroll
    for (int mi = 0; mi < 4; mi++) aoff[mi] = (a_row + mi * 16) * LDA + a_col;
    int b_row = n0 + (lane & 7) + ((lane >> 4) & 1) * 8;
    int b_col = ((lane >> 3) & 1) * 8;
    int boff[2];
#pragma unroll
    for (int p = 0; p < 2; p++) boff[p] = (b_row + p * 16) * LDA + b_col;

    const uint32_t sb = smem_u32(sm);

    float acc0[4][4][4];
    float acc1[4][4][4];
#pragma unroll
    for (int a = 0; a < 4; a++)
#pragma unroll
        for (int b = 0; b < 4; b++)
#pragma unroll
            for (int e = 0; e < 4; e++) { acc0[a][b][e] = 0.f; acc1[a][b][e] = 0.f; }

    auto load_tile = [&](int kt, int s) {
        uint32_t st = sb + (uint32_t)(s * STG) * 2;
        int k0 = kt * 64;
#pragma unroll
        for (int u = 0; u < 4; u++) {
            int id = u * 256 + tid;
            int row = id >> 3, ch = id & 7;
            cp16(st + row * (LDA * 2) + ch * 16,
                 Ag + (size_t)row * lda + k0 + ch * 8);
        }
#pragma unroll
        for (int u = 0; u < 4; u++) {
            int id = u * 256 + tid;
            int row = id >> 3, ch = id & 7;
            cp16(st + TSZ * 2 + row * (LDA * 2) + ch * 16,
                 Bg0 + (size_t)row * ldb + k0 + ch * 8);
        }
#pragma unroll
        for (int u = 0; u < 4; u++) {
            int id = u * 256 + tid;
            int row = id >> 3, ch = id & 7;
            cp16(st + TSZ * 4 + row * (LDA * 2) + ch * 16,
                 Bg1 + (size_t)row * ldb + k0 + ch * 8);
        }
        asm volatile("cp.async.commit_group;" ::: "memory");
    };

    load_tile(0, 0);
    load_tile(1, 1);

    // register fragment ping-pong buffers
    uint32_t af[2][4][4], bf0[2][4][2], bf1[2][4][2];

    int stage = 0;
    for (int kt = 0; kt < KT; kt++) {
        if (kt + 1 < KT) asm volatile("cp.async.wait_group 1;" ::: "memory");
        else             asm volatile("cp.async.wait_group 0;" ::: "memory");
        __syncthreads();

        if (kt + 2 < KT) {
            int ns = stage + 2; if (ns >= 3) ns -= 3;
            load_tile(kt + 2, ns);
        }

        uint32_t ab  = sb + (uint32_t)(stage * STG) * 2;
        uint32_t bb0 = ab + TSZ * 2;
        uint32_t bb1 = ab + TSZ * 4;

        auto ld_frags = [&](int ks16, int pb) {
#pragma unroll
            for (int mi = 0; mi < 4; mi++)
                ldsm4(af[pb][mi][0], af[pb][mi][1], af[pb][mi][2], af[pb][mi][3],
                      ab + (uint32_t)(aoff[mi] + ks16) * 2);
#pragma unroll
            for (int p = 0; p < 2; p++)
                ldsm4(bf0[pb][2 * p][0], bf0[pb][2 * p][1],
                      bf0[pb][2 * p + 1][0], bf0[pb][2 * p + 1][1],
                      bb0 + (uint32_t)(boff[p] + ks16) * 2);
#pragma unroll
            for (int p = 0; p < 2; p++)
                ldsm4(bf1[pb][2 * p][0], bf1[pb][2 * p][1],
                      bf1[pb][2 * p + 1][0], bf1[pb][2 * p + 1][1],
                      bb1 + (uint32_t)(boff[p] + ks16) * 2);
        };

        ld_frags(0, 0);
#pragma unroll
        for (int ksid = 0; ksid < 4; ksid++) {
            const int cur = ksid & 1;
            if (ksid < 3) ld_frags((ksid + 1) * 16, cur ^ 1);
#pragma unroll
            for (int mi = 0; mi < 4; mi++)
#pragma unroll
                for (int ni = 0; ni < 4; ni++) {
                    mma16816(acc0[mi][ni], af[cur][mi], bf0[cur][ni]);
                    mma16816(acc1[mi][ni], af[cur][mi], bf1[cur][ni]);
                }
        }
        stage++; if (stage >= 3) stage = 0;
    }

    // epilogue
    const float s0 = g_scales[sbase];
    const float s1 = (EPI == 0) ? g_scales[sbase + 1] : s0;
    const int grp = lane >> 2, tig = lane & 3;

    if constexpr (EPI == 0) {
        const bool edge = ((blockIdx.x + 1) * 128 > (unsigned)Nvalid);
#pragma unroll
        for (int mi = 0; mi < 4; mi++) {
#pragma unroll
            for (int ni = 0; ni < 4; ni++) {
                int rbase = blockIdx.y * 128 + m0 + mi * 16 + grp;
                int cb    = blockIdx.x * 128 + n0 + ni * 8 + tig * 2;
#pragma unroll
                for (int half_e = 0; half_e < 2; half_e++) {
                    int r = rbase + half_e * 8;
                    float g = acc0[mi][ni][half_e * 2 + 0] * s0;
                    float u = acc1[mi][ni][half_e * 2 + 0] * s1;
                    float h0 = u * (g / (1.f + __expf(-g)));
                    g = acc0[mi][ni][half_e * 2 + 1] * s0;
                    u = acc1[mi][ni][half_e * 2 + 1] * s1;
                    float h1 = u * (g / (1.f + __expf(-g)));
                    if (!edge || cb < Nvalid)
                        *(__half2*)(Ch + (size_t)r * ldc + cb) =
                            __floats2half2_rn(h0, h1);
                }
            }
        }
    } else {
#pragma unroll
        for (int mi = 0; mi < 4; mi++) {
#pragma unroll
            for (int ni = 0; ni < 4; ni++) {
                int rbase = blockIdx.y * 128 + m0 + mi * 16 + grp;
                int cb0   = blockIdx.x * 256 + n0 + ni * 8 + tig * 2;
#pragma unroll
                for (int half_e = 0; half_e < 2; half_e++) {
                    int r = rbase + half_e * 8;
                    float2 v0, v1;
                    v0.x = acc0[mi][ni][half_e * 2 + 0] * s0;
                    v0.y = acc0[mi][ni][half_e * 2 + 1] * s0;
                    v1.x = acc1[mi][ni][half_e * 2 + 0] * s0;
                    v1.y = acc1[mi][ni][half_e * 2 + 1] * s0;
                    *(float2*)(Cf + (size_t)r * ldc + cb0)       = v0;
                    *(float2*)(Cf + (size_t)r * ldc + cb0 + 128) = v1;
                }
            }
        }
    }
}

// ---------------------------------------------------------------------------
// launcher
// ---------------------------------------------------------------------------
extern "C" void kernel_launch(void* const* d_in, const int* in_sizes, int n_in,
                              void* d_out, int out_size) {
    (void)in_sizes; (void)n_in; (void)out_size;
    const float* x  = (const float*)d_in[0];
    const float* wg = (const float*)d_in[1];
    const float* wu = (const float*)d_in[2];
    const float* wd = (const float*)d_in[3];
    float* out = (float*)d_out;

    void* p;
    cudaGetSymbolAddress(&p, g_Mg); __half* Mg = (__half*)p;
    cudaGetSymbolAddress(&p, g_Mu); __half* Mu = (__half*)p;
    cudaGetSymbolAddress(&p, g_Md); __half* Md = (__half*)p;
    cudaGetSymbolAddress(&p, g_X);  __half* X  = (__half*)p;
    cudaGetSymbolAddress(&p, g_H);  __half* Hb = (__half*)p;

    reduce_abs_kernel<<<dim3(256, 3), 256>>>(wg, wu, wd, WN);          // launch 1
    finalize_scales_kernel<<<1, 256>>>(WN);                            // launch 2

    int total_items = 2 * GU_ITEMS + D_ITEMS + X_ITEMS;
    build_all_kernel<<<(total_items + 255) / 256, 256>>>(              // launch 3
        Mg, Mu, Md, X, wg, wu, wd, x);

    constexpr int SMEM = 3 * (128 * 72 * 3) * (int)sizeof(__half);     // 165888
    cudaFuncSetAttribute((const void*)hgemm<0>,
                         cudaFuncAttributeMaxDynamicSharedMemorySize, SMEM);
    cudaFuncSetAttribute((const void*)hgemm<1>,
                         cudaFuncAttributeMaxDynamicSharedMemorySize, SMEM);

    // fused gate+up -> H (fp16)                                       // launch 4
    hgemm<0><<<dim3(NH_PAD / 128, MROWS / 128), 256, SMEM>>>(
        X, KD, Mg, KD, Hb, nullptr, K2, NH, KD / 64, 0, 0, Mu);

    // down two-strip -> out (fp32)                                    // launch 5
    hgemm<1><<<dim3(4096 / 256, MROWS / 128), 256, SMEM>>>(
        Hb, K2, Md, K2, nullptr, out, 4096, 4096, K2 / 64, 2, 256, nullptr);
}

// round 8
// speedup vs baseline: 1.6738x; 1.1531x over previous
#include <cuda_runtime.h>
#include <cuda_fp16.h>
#include <cstdint>
#include <cstddef>

// ---------------------------------------------------------------------------
// out = silu(x@Mg^T)*(x@Mu^T) @ Md^T, ternary-dequant octonion weights.
// Octonion structure collapses to j = i XOR k + sign LUT.
// R8: occupancy 2 CTA/SM (4 warps/SMSP). BM=128, BN=64 dual-B, BK=64,
//     3-stage cp.async, single-buffer frags, <=128 regs.
// ---------------------------------------------------------------------------

static constexpr int MROWS = 4096, KD = 4096, NH = 10928, NH_PAD = 11008, K2 = 10944;
static constexpr int WN = 8 * 1366 * 512;

__device__ __half g_Mg[(size_t)NH_PAD * KD];
__device__ __half g_Mu[(size_t)NH_PAD * KD];
__device__ __half g_Md[(size_t)4096 * K2];
__device__ __half g_X [(size_t)MROWS * KD];
__device__ __half g_H [(size_t)MROWS * K2];
__device__ float  g_red[3 * 256];
__device__ float  g_scales[3];

// sign LUT: s[i*8+k] = S[i^k, i, k]
__constant__ float c_S[64] = {
 +1,+1,+1,+1,+1,+1,+1,+1,
 -1,+1,+1,-1,+1,-1,-1,+1,
 -1,-1,+1,+1,+1,+1,-1,-1,
 -1,+1,-1,+1,+1,-1,+1,-1,
 -1,-1,-1,-1,+1,+1,+1,+1,
 -1,+1,-1,+1,-1,+1,-1,+1,
 -1,+1,+1,-1,-1,+1,+1,-1,
 -1,-1,+1,+1,-1,-1,+1,+1};

// ---------------------------------------------------------------------------
// scales
// ---------------------------------------------------------------------------
__global__ void reduce_abs_kernel(const float* __restrict__ w0,
                                  const float* __restrict__ w1,
                                  const float* __restrict__ w2, int n) {
    int t = blockIdx.y;
    const float* w = (t == 0) ? w0 : (t == 1 ? w1 : w2);
    float s = 0.f;
    for (int i = blockIdx.x * blockDim.x + threadIdx.x; i < n;
         i += gridDim.x * blockDim.x)
        s += fabsf(w[i]);
    __shared__ float sh[256];
    sh[threadIdx.x] = s;
    __syncthreads();
    for (int st = 128; st > 0; st >>= 1) {
        if (threadIdx.x < st) sh[threadIdx.x] += sh[threadIdx.x + st];
        __syncthreads();
    }
    if (threadIdx.x == 0) g_red[t * 256 + blockIdx.x] = sh[0];
}

__global__ void finalize_scales_kernel(int n) {
    __shared__ float sh[256];
    for (int t = 0; t < 3; t++) {
        sh[threadIdx.x] = g_red[t * 256 + threadIdx.x];
        __syncthreads();
        for (int st = 128; st > 0; st >>= 1) {
            if (threadIdx.x < st) sh[threadIdx.x] += sh[threadIdx.x + st];
            __syncthreads();
        }
        if (threadIdx.x == 0) g_scales[t] = sh[0] / (float)n;
        __syncthreads();
    }
}

// ---------------------------------------------------------------------------
// merged build: Mg, Mu, Md + x -> fp16
// ---------------------------------------------------------------------------
static constexpr int GU_ITEMS = NH * 512;
static constexpr int D_ITEMS  = 4096 * (K2 / 8);
static constexpr int X_ITEMS  = MROWS * KD / 8;

__global__ void build_all_kernel(__half* __restrict__ Mg, __half* __restrict__ Mu,
                                 __half* __restrict__ Md, __half* __restrict__ X,
                                 const float* __restrict__ wg,
                                 const float* __restrict__ wu,
                                 const float* __restrict__ wd,
                                 const float* __restrict__ x) {
    int id = blockIdx.x * blockDim.x + threadIdx.x;
    if (id < 2 * GU_ITEMS) {
        const float* W = (id < GU_ITEMS) ? wg : wu;
        __half* out    = (id < GU_ITEMS) ? Mg : Mu;
        float s        = (id < GU_ITEMS) ? g_scales[0] : g_scales[1];
        int t  = (id < GU_ITEMS) ? id : id - GU_ITEMS;
        int r  = t >> 9;
        int c  = (t & 511) * 8;
        int k = r / 1366, o = r - k * 1366;
        int i = c >> 9, d = c & 511;
        int j = i ^ k;
        float sg = c_S[i * 8 + k];
        const float4* src = (const float4*)(W + ((size_t)(j * 1366 + o)) * 512 + d);
        float4 v0 = src[0], v1 = src[1];
        float q[8] = {v0.x, v0.y, v0.z, v0.w, v1.x, v1.y, v1.z, v1.w};
        __align__(16) __half h[8];
#pragma unroll
        for (int tt = 0; tt < 8; tt++) {
            float qq = rintf(q[tt] / s);
            qq = fminf(1.f, fmaxf(-1.f, qq)) * sg;
            h[tt] = __float2half_rn(qq);
        }
        *(uint4*)(out + (size_t)r * 4096 + c) = *(uint4*)h;
        return;
    }
    int t = id - 2 * GU_ITEMS;
    if (t < D_ITEMS) {
        int r = t / (K2 / 8);
        int c = (t - r * (K2 / 8)) * 8;
        int k = r >> 9, o = r & 511;
        float s = g_scales[2];
        __align__(16) __half h[8];
#pragma unroll
        for (int tt = 0; tt < 8; tt++) {
            int cc = c + tt;
            if (cc < NH) {
                int i = cc / 1366, d = cc - i * 1366;
                int j = i ^ k;
                float sg = c_S[i * 8 + k];
                float q = rintf(wd[((size_t)(j * 512 + o)) * 1366 + d] / s);
                h[tt] = __float2half_rn(fminf(1.f, fmaxf(-1.f, q)) * sg);
            } else {
                h[tt] = __float2half_rn(0.f);
            }
        }
        *(uint4*)(Md + (size_t)r * K2 + c) = *(uint4*)h;
        return;
    }
    t -= D_ITEMS;
    if (t >= X_ITEMS) return;
    const float4* src = (const float4*)(x + (size_t)t * 8);
    float4 v0 = src[0], v1 = src[1];
    __align__(16) __half h[8];
    *(__half2*)(h + 0) = __floats2half2_rn(v0.x, v0.y);
    *(__half2*)(h + 2) = __floats2half2_rn(v0.z, v0.w);
    *(__half2*)(h + 4) = __floats2half2_rn(v1.x, v1.y);
    *(__half2*)(h + 6) = __floats2half2_rn(v1.z, v1.w);
    *(uint4*)(X + (size_t)t * 8) = *(uint4*)h;
}

// ---------------------------------------------------------------------------
// GEMM helpers
// ---------------------------------------------------------------------------
__device__ __forceinline__ uint32_t smem_u32(const void* p) {
    return (uint32_t)__cvta_generic_to_shared(p);
}
__device__ __forceinline__ void cp16(uint32_t s, const void* g) {
    asm volatile("cp.async.cg.shared.global [%0], [%1], 16;\n" :: "r"(s), "l"(g));
}
__device__ __forceinline__ void ldsm4(uint32_t& r0, uint32_t& r1, uint32_t& r2,
                                      uint32_t& r3, uint32_t addr) {
    asm volatile("ldmatrix.sync.aligned.m8n8.x4.shared.b16 {%0,%1,%2,%3}, [%4];"
                 : "=r"(r0), "=r"(r1), "=r"(r2), "=r"(r3) : "r"(addr));
}
__device__ __forceinline__ void mma16816(float c[4], const uint32_t a[4],
                                         const uint32_t b[2]) {
    asm("mma.sync.aligned.m16n8k16.row.col.f32.f16.f16.f32 "
        "{%0,%1,%2,%3}, {%4,%5,%6,%7}, {%8,%9}, {%0,%1,%2,%3};\n"
        : "+f"(c[0]), "+f"(c[1]), "+f"(c[2]), "+f"(c[3])
        : "r"(a[0]), "r"(a[1]), "r"(a[2]), "r"(a[3]), "r"(b[0]), "r"(b[1]));
}

// ---------------------------------------------------------------------------
// Dual-B HMMA GEMM, occupancy-2 variant.
// Per CTA: A(128 x K) vs B0,B1 (64 x K each).  Warp tile: 64x16 per B.
// EPI=0: B0=gate strip, B1=up strip -> silu(g)*u -> fp16 H (64 cols/CTA)
// EPI=1: B0,B1 = adjacent 64-row strips of Md -> fp32 out (128 cols/CTA)
// ---------------------------------------------------------------------------
template <int EPI>
__global__ void __launch_bounds__(256, 2)
hgemm(const __half* __restrict__ A, int lda,
      const __half* __restrict__ Bbase, int ldb,
      __half* __restrict__ Ch, float* __restrict__ Cf, int ldc,
      int Nvalid, int KT, int sbase,
      const __half* __restrict__ B1base) {
    extern __shared__ __align__(16) __half sm[];
    constexpr int LDA = 72;
    constexpr int A_T = 128 * LDA;          // halfs
    constexpr int B_T = 64 * LDA;
    constexpr int STG = A_T + 2 * B_T;

    const int tid  = threadIdx.x;
    const int warp = tid >> 5, lane = tid & 31;
    const int wm = warp >> 2, wn = warp & 3;
    const int m0 = wm * 64, n0 = wn * 16;

    const __half* Ag = A + (size_t)blockIdx.y * 128 * lda;
    const __half* Bg0;
    const __half* Bg1;
    if (EPI == 0) {
        Bg0 = Bbase  + (size_t)blockIdx.x * 64 * ldb;
        Bg1 = B1base + (size_t)blockIdx.x * 64 * ldb;
    } else {
        Bg0 = Bbase + (size_t)blockIdx.x * 128 * ldb;
        Bg1 = Bg0 + (size_t)64 * ldb;
    }

    int a_row = m0 + (lane & 7) + ((lane >> 3) & 1) * 8;
    int a_col = (lane >> 4) * 8;
    int aoff[4];
#pragma unroll
    for (int mi = 0; mi < 4; mi++) aoff[mi] = (a_row + mi * 16) * LDA + a_col;
    int b_row = n0 + (lane & 7) + ((lane >> 4) & 1) * 8;
    int b_col = ((lane >> 3) & 1) * 8;
    const int boff = b_row * LDA + b_col;

    const uint32_t sb = smem_u32(sm);

    float acc0[4][2][4];
    float acc1[4][2][4];
#pragma unroll
    for (int a = 0; a < 4; a++)
#pragma unroll
        for (int b = 0; b < 2; b++)
#pragma unroll
            for (int e = 0; e < 4; e++) { acc0[a][b][e] = 0.f; acc1[a][b][e] = 0.f; }

    auto load_tile = [&](int kt, int s) {
        uint32_t st = sb + (uint32_t)(s * STG) * 2;
        int k0 = kt * 64;
#pragma unroll
        for (int u = 0; u < 4; u++) {            // A: 1024 chunks
            int id = u * 256 + tid;
            int row = id >> 3, ch = id & 7;
            cp16(st + row * (LDA * 2) + ch * 16,
                 Ag + (size_t)row * lda + k0 + ch * 8);
        }
#pragma unroll
        for (int u = 0; u < 2; u++) {            // B0: 512 chunks
            int id = u * 256 + tid;
            int row = id >> 3, ch = id & 7;
            cp16(st + A_T * 2 + row * (LDA * 2) + ch * 16,
                 Bg0 + (size_t)row * ldb + k0 + ch * 8);
        }
#pragma unroll
        for (int u = 0; u < 2; u++) {            // B1
            int id = u * 256 + tid;
            int row = id >> 3, ch = id & 7;
            cp16(st + (A_T + B_T) * 2 + row * (LDA * 2) + ch * 16,
                 Bg1 + (size_t)row * ldb + k0 + ch * 8);
        }
        asm volatile("cp.async.commit_group;" ::: "memory");
    };

    load_tile(0, 0);
    load_tile(1, 1);

    int stage = 0;
    for (int kt = 0; kt < KT; kt++) {
        if (kt + 1 < KT) asm volatile("cp.async.wait_group 1;" ::: "memory");
        else             asm volatile("cp.async.wait_group 0;" ::: "memory");
        __syncthreads();

        if (kt + 2 < KT) {
            int ns = stage + 2; if (ns >= 3) ns -= 3;
            load_tile(kt + 2, ns);
        }

        uint32_t ab  = sb + (uint32_t)(stage * STG) * 2;
        uint32_t bb0 = ab + A_T * 2;
        uint32_t bb1 = ab + (A_T + B_T) * 2;

#pragma unroll
        for (int ksid = 0; ksid < 4; ksid++) {
            const int ks = ksid * 16;
            uint32_t af[4][4];
#pragma unroll
            for (int mi = 0; mi < 4; mi++)
                ldsm4(af[mi][0], af[mi][1], af[mi][2], af[mi][3],
                      ab + (uint32_t)(aoff[mi] + ks) * 2);
            uint32_t bf0[2][2], bf1[2][2];
            ldsm4(bf0[0][0], bf0[0][1], bf0[1][0], bf0[1][1],
                  bb0 + (uint32_t)(boff + ks) * 2);
            ldsm4(bf1[0][0], bf1[0][1], bf1[1][0], bf1[1][1],
                  bb1 + (uint32_t)(boff + ks) * 2);
#pragma unroll
            for (int mi = 0; mi < 4; mi++)
#pragma unroll
                for (int ni = 0; ni < 2; ni++) {
                    mma16816(acc0[mi][ni], af[mi], bf0[ni]);
                    mma16816(acc1[mi][ni], af[mi], bf1[ni]);
                }
        }
        stage++; if (stage >= 3) stage = 0;
    }

    // epilogue
    const float s0 = g_scales[sbase];
    const float s1 = (EPI == 0) ? g_scales[sbase + 1] : s0;
    const int grp = lane >> 2, tig = lane & 3;

    if constexpr (EPI == 0) {
        const bool edge = ((blockIdx.x + 1) * 64 > (unsigned)Nvalid);
#pragma unroll
        for (int mi = 0; mi < 4; mi++) {
#pragma unroll
            for (int ni = 0; ni < 2; ni++) {
                int rbase = blockIdx.y * 128 + m0 + mi * 16 + grp;
                int cb    = blockIdx.x * 64 + n0 + ni * 8 + tig * 2;
#pragma unroll
                for (int he = 0; he < 2; he++) {
                    int r = rbase + he * 8;
                    float g = acc0[mi][ni][he * 2 + 0] * s0;
                    float u = acc1[mi][ni][he * 2 + 0] * s1;
                    float h0 = u * (g / (1.f + __expf(-g)));
                    g = acc0[mi][ni][he * 2 + 1] * s0;
                    u = acc1[mi][ni][he * 2 + 1] * s1;
                    float h1 = u * (g / (1.f + __expf(-g)));
                    if (!edge || cb < Nvalid)
                        *(__half2*)(Ch + (size_t)r * ldc + cb) =
                            __floats2half2_rn(h0, h1);
                }
            }
        }
    } else {
#pragma unroll
        for (int mi = 0; mi < 4; mi++) {
#pragma unroll
            for (int ni = 0; ni < 2; ni++) {
                int rbase = blockIdx.y * 128 + m0 + mi * 16 + grp;
                int cb0   = blockIdx.x * 128 + n0 + ni * 8 + tig * 2;
#pragma unroll
                for (int he = 0; he < 2; he++) {
                    int r = rbase + he * 8;
                    float2 v0, v1;
                    v0.x = acc0[mi][ni][he * 2 + 0] * s0;
                    v0.y = acc0[mi][ni][he * 2 + 1] * s0;
                    v1.x = acc1[mi][ni][he * 2 + 0] * s0;
                    v1.y = acc1[mi][ni][he * 2 + 1] * s0;
                    *(float2*)(Cf + (size_t)r * ldc + cb0)      = v0;
                    *(float2*)(Cf + (size_t)r * ldc + cb0 + 64) = v1;
                }
            }
        }
    }
}

// ---------------------------------------------------------------------------
// launcher
// ---------------------------------------------------------------------------
extern "C" void kernel_launch(void* const* d_in, const int* in_sizes, int n_in,
                              void* d_out, int out_size) {
    (void)in_sizes; (void)n_in; (void)out_size;
    const float* x  = (const float*)d_in[0];
    const float* wg = (const float*)d_in[1];
    const float* wu = (const float*)d_in[2];
    const float* wd = (const float*)d_in[3];
    float* out = (float*)d_out;

    void* p;
    cudaGetSymbolAddress(&p, g_Mg); __half* Mg = (__half*)p;
    cudaGetSymbolAddress(&p, g_Mu); __half* Mu = (__half*)p;
    cudaGetSymbolAddress(&p, g_Md); __half* Md = (__half*)p;
    cudaGetSymbolAddress(&p, g_X);  __half* X  = (__half*)p;
    cudaGetSymbolAddress(&p, g_H);  __half* Hb = (__half*)p;

    reduce_abs_kernel<<<dim3(256, 3), 256>>>(wg, wu, wd, WN);
    finalize_scales_kernel<<<1, 256>>>(WN);

    int total_items = 2 * GU_ITEMS + D_ITEMS + X_ITEMS;
    build_all_kernel<<<(total_items + 255) / 256, 256>>>(
        Mg, Mu, Md, X, wg, wu, wd, x);

    constexpr int SMEM = 3 * (128 * 72 + 2 * 64 * 72) * (int)sizeof(__half); // 110592
    cudaFuncSetAttribute((const void*)hgemm<0>,
                         cudaFuncAttributeMaxDynamicSharedMemorySize, SMEM);
    cudaFuncSetAttribute((const void*)hgemm<1>,
                         cudaFuncAttributeMaxDynamicSharedMemorySize, SMEM);

    // fused gate+up -> H (fp16); 64 hidden cols per CTA
    hgemm<0><<<dim3(NH_PAD / 64, MROWS / 128), 256, SMEM>>>(
        X, KD, Mg, KD, Hb, nullptr, K2, NH, KD / 64, 0, Mu);

    // down (two 64-row strips of Md per CTA) -> out (fp32)
    hgemm<1><<<dim3(4096 / 128, MROWS / 128), 256, SMEM>>>(
        Hb, K2, Md, K2, nullptr, out, 4096, 4096, K2 / 64, 2, nullptr);
}

// round 9
// speedup vs baseline: 1.6931x; 1.0115x over previous
#include <cuda_runtime.h>
#include <cuda_fp16.h>
#include <cstdint>
#include <cstddef>

// ---------------------------------------------------------------------------
// out = silu(x@Mg^T)*(x@Mu^T) @ Md^T, ternary-dequant octonion weights.
// Octonion structure collapses to j = i XOR k + sign LUT.
// R9: grid transposed (bx = M-tile fast) so a wave's working set (A 32MB +
//     ~9 B strips) fits L2 and each B strip hits DRAM once. Build kernel
//     uses reciprocal multiply + incremental index walk.
// ---------------------------------------------------------------------------

static constexpr int MROWS = 4096, KD = 4096, NH = 10928, NH_PAD = 11008, K2 = 10944;
static constexpr int WN = 8 * 1366 * 512;

__device__ __half g_Mg[(size_t)NH_PAD * KD];
__device__ __half g_Mu[(size_t)NH_PAD * KD];
__device__ __half g_Md[(size_t)4096 * K2];
__device__ __half g_X [(size_t)MROWS * KD];
__device__ __half g_H [(size_t)MROWS * K2];
__device__ float  g_red[3 * 256];
__device__ float  g_scales[3];
__device__ float  g_inv[3];

// sign LUT: s[i*8+k] = S[i^k, i, k]
__constant__ float c_S[64] = {
 +1,+1,+1,+1,+1,+1,+1,+1,
 -1,+1,+1,-1,+1,-1,-1,+1,
 -1,-1,+1,+1,+1,+1,-1,-1,
 -1,+1,-1,+1,+1,-1,+1,-1,
 -1,-1,-1,-1,+1,+1,+1,+1,
 -1,+1,-1,+1,-1,+1,-1,+1,
 -1,+1,+1,-1,-1,+1,+1,-1,
 -1,-1,+1,+1,-1,-1,+1,+1};

// ---------------------------------------------------------------------------
// scales
// ---------------------------------------------------------------------------
__global__ void reduce_abs_kernel(const float* __restrict__ w0,
                                  const float* __restrict__ w1,
                                  const float* __restrict__ w2, int n) {
    int t = blockIdx.y;
    const float* w = (t == 0) ? w0 : (t == 1 ? w1 : w2);
    float s = 0.f;
    for (int i = blockIdx.x * blockDim.x + threadIdx.x; i < n;
         i += gridDim.x * blockDim.x)
        s += fabsf(w[i]);
    __shared__ float sh[256];
    sh[threadIdx.x] = s;
    __syncthreads();
    for (int st = 128; st > 0; st >>= 1) {
        if (threadIdx.x < st) sh[threadIdx.x] += sh[threadIdx.x + st];
        __syncthreads();
    }
    if (threadIdx.x == 0) g_red[t * 256 + blockIdx.x] = sh[0];
}

__global__ void finalize_scales_kernel(int n) {
    __shared__ float sh[256];
    for (int t = 0; t < 3; t++) {
        sh[threadIdx.x] = g_red[t * 256 + threadIdx.x];
        __syncthreads();
        for (int st = 128; st > 0; st >>= 1) {
            if (threadIdx.x < st) sh[threadIdx.x] += sh[threadIdx.x + st];
            __syncthreads();
        }
        if (threadIdx.x == 0) {
            float sc = sh[0] / (float)n;
            g_scales[t] = sc;
            g_inv[t]    = 1.0f / sc;
        }
        __syncthreads();
    }
}

// ---------------------------------------------------------------------------
// merged build: Mg, Mu, Md + x -> fp16
// ---------------------------------------------------------------------------
static constexpr int GU_ITEMS = NH * 512;
static constexpr int D_ITEMS  = 4096 * (K2 / 8);
static constexpr int X_ITEMS  = MROWS * KD / 8;

__global__ void build_all_kernel(__half* __restrict__ Mg, __half* __restrict__ Mu,
                                 __half* __restrict__ Md, __half* __restrict__ X,
                                 const float* __restrict__ wg,
                                 const float* __restrict__ wu,
                                 const float* __restrict__ wd,
                                 const float* __restrict__ x) {
    int id = blockIdx.x * blockDim.x + threadIdx.x;
    if (id < 2 * GU_ITEMS) {
        const float* W = (id < GU_ITEMS) ? wg : wu;
        __half* out    = (id < GU_ITEMS) ? Mg : Mu;
        float inv      = (id < GU_ITEMS) ? g_inv[0] : g_inv[1];
        int t  = (id < GU_ITEMS) ? id : id - GU_ITEMS;
        int r  = t >> 9;
        int c  = (t & 511) * 8;
        int k = r / 1366, o = r - k * 1366;
        int i = c >> 9, d = c & 511;
        int j = i ^ k;
        float sg = c_S[i * 8 + k];
        const float4* src = (const float4*)(W + ((size_t)(j * 1366 + o)) * 512 + d);
        float4 v0 = src[0], v1 = src[1];
        float q[8] = {v0.x, v0.y, v0.z, v0.w, v1.x, v1.y, v1.z, v1.w};
        __align__(16) __half h[8];
#pragma unroll
        for (int tt = 0; tt < 8; tt++) {
            float qq = rintf(q[tt] * inv);
            qq = fminf(1.f, fmaxf(-1.f, qq)) * sg;
            h[tt] = __float2half_rn(qq);
        }
        *(uint4*)(out + (size_t)r * 4096 + c) = *(uint4*)h;
        return;
    }
    int t = id - 2 * GU_ITEMS;
    if (t < D_ITEMS) {
        int r = t / (K2 / 8);
        int c = (t - r * (K2 / 8)) * 8;
        int k = r >> 9, o = r & 511;
        float inv = g_inv[2];
        int i = c / 1366, d = c - i * 1366;
        __align__(16) __half h[8];
#pragma unroll
        for (int tt = 0; tt < 8; tt++) {
            int cc = c + tt;
            if (cc < NH) {
                int j = i ^ k;
                float sg = c_S[i * 8 + k];
                float q = rintf(wd[((size_t)(j * 512 + o)) * 1366 + d] * inv);
                h[tt] = __float2half_rn(fminf(1.f, fmaxf(-1.f, q)) * sg);
            } else {
                h[tt] = __float2half_rn(0.f);
            }
            if (++d == 1366) { d = 0; ++i; }
        }
        *(uint4*)(Md + (size_t)r * K2 + c) = *(uint4*)h;
        return;
    }
    t -= D_ITEMS;
    if (t >= X_ITEMS) return;
    const float4* src = (const float4*)(x + (size_t)t * 8);
    float4 v0 = src[0], v1 = src[1];
    __align__(16) __half h[8];
    *(__half2*)(h + 0) = __floats2half2_rn(v0.x, v0.y);
    *(__half2*)(h + 2) = __floats2half2_rn(v0.z, v0.w);
    *(__half2*)(h + 4) = __floats2half2_rn(v1.x, v1.y);
    *(__half2*)(h + 6) = __floats2half2_rn(v1.z, v1.w);
    *(uint4*)(X + (size_t)t * 8) = *(uint4*)h;
}

// ---------------------------------------------------------------------------
// GEMM helpers
// ---------------------------------------------------------------------------
__device__ __forceinline__ uint32_t smem_u32(const void* p) {
    return (uint32_t)__cvta_generic_to_shared(p);
}
__device__ __forceinline__ void cp16(uint32_t s, const void* g) {
    asm volatile("cp.async.cg.shared.global [%0], [%1], 16;\n" :: "r"(s), "l"(g));
}
__device__ __forceinline__ void ldsm4(uint32_t& r0, uint32_t& r1, uint32_t& r2,
                                      uint32_t& r3, uint32_t addr) {
    asm volatile("ldmatrix.sync.aligned.m8n8.x4.shared.b16 {%0,%1,%2,%3}, [%4];"
                 : "=r"(r0), "=r"(r1), "=r"(r2), "=r"(r3) : "r"(addr));
}
__device__ __forceinline__ void mma16816(float c[4], const uint32_t a[4],
                                         const uint32_t b[2]) {
    asm("mma.sync.aligned.m16n8k16.row.col.f32.f16.f16.f32 "
        "{%0,%1,%2,%3}, {%4,%5,%6,%7}, {%8,%9}, {%0,%1,%2,%3};\n"
        : "+f"(c[0]), "+f"(c[1]), "+f"(c[2]), "+f"(c[3])
        : "r"(a[0]), "r"(a[1]), "r"(a[2]), "r"(a[3]), "r"(b[0]), "r"(b[1]));
}

// ---------------------------------------------------------------------------
// Dual-B HMMA GEMM, occupancy-2, TRANSPOSED grid:
//   blockIdx.x = M-tile (fast-varying -> wave shares A in L2)
//   blockIdx.y = N-strip (slow -> each B strip DRAM-read ~once)
// EPI=0: B0=gate strip, B1=up strip -> silu(g)*u -> fp16 H (64 cols/CTA)
// EPI=1: B0,B1 = adjacent 64-row strips of Md -> fp32 out (128 cols/CTA)
// ---------------------------------------------------------------------------
template <int EPI>
__global__ void __launch_bounds__(256, 2)
hgemm(const __half* __restrict__ A, int lda,
      const __half* __restrict__ Bbase, int ldb,
      __half* __restrict__ Ch, float* __restrict__ Cf, int ldc,
      int Nvalid, int KT, int sbase,
      const __half* __restrict__ B1base) {
    extern __shared__ __align__(16) __half sm[];
    constexpr int LDA = 72;
    constexpr int A_T = 128 * LDA;
    constexpr int B_T = 64 * LDA;
    constexpr int STG = A_T + 2 * B_T;

    const int tid  = threadIdx.x;
    const int warp = tid >> 5, lane = tid & 31;
    const int wm = warp >> 2, wn = warp & 3;
    const int m0 = wm * 64, n0 = wn * 16;

    const int mt = blockIdx.x;          // M tile
    const int nt = blockIdx.y;          // N strip

    const __half* Ag = A + (size_t)mt * 128 * lda;
    const __half* Bg0;
    const __half* Bg1;
    if (EPI == 0) {
        Bg0 = Bbase  + (size_t)nt * 64 * ldb;
        Bg1 = B1base + (size_t)nt * 64 * ldb;
    } else {
        Bg0 = Bbase + (size_t)nt * 128 * ldb;
        Bg1 = Bg0 + (size_t)64 * ldb;
    }

    int a_row = m0 + (lane & 7) + ((lane >> 3) & 1) * 8;
    int a_col = (lane >> 4) * 8;
    int aoff[4];
#pragma unroll
    for (int mi = 0; mi < 4; mi++) aoff[mi] = (a_row + mi * 16) * LDA + a_col;
    int b_row = n0 + (lane & 7) + ((lane >> 4) & 1) * 8;
    int b_col = ((lane >> 3) & 1) * 8;
    const int boff = b_row * LDA + b_col;

    const uint32_t sb = smem_u32(sm);

    float acc0[4][2][4];
    float acc1[4][2][4];
#pragma unroll
    for (int a = 0; a < 4; a++)
#pragma unroll
        for (int b = 0; b < 2; b++)
#pragma unroll
            for (int e = 0; e < 4; e++) { acc0[a][b][e] = 0.f; acc1[a][b][e] = 0.f; }

    auto load_tile = [&](int kt, int s) {
        uint32_t st = sb + (uint32_t)(s * STG) * 2;
        int k0 = kt * 64;
#pragma unroll
        for (int u = 0; u < 4; u++) {
            int id = u * 256 + tid;
            int row = id >> 3, ch = id & 7;
            cp16(st + row * (LDA * 2) + ch * 16,
                 Ag + (size_t)row * lda + k0 + ch * 8);
        }
#pragma unroll
        for (int u = 0; u < 2; u++) {
            int id = u * 256 + tid;
            int row = id >> 3, ch = id & 7;
            cp16(st + A_T * 2 + row * (LDA * 2) + ch * 16,
                 Bg0 + (size_t)row * ldb + k0 + ch * 8);
        }
#pragma unroll
        for (int u = 0; u < 2; u++) {
            int id = u * 256 + tid;
            int row = id >> 3, ch = id & 7;
            cp16(st + (A_T + B_T) * 2 + row * (LDA * 2) + ch * 16,
                 Bg1 + (size_t)row * ldb + k0 + ch * 8);
        }
        asm volatile("cp.async.commit_group;" ::: "memory");
    };

    load_tile(0, 0);
    load_tile(1, 1);

    int stage = 0;
    for (int kt = 0; kt < KT; kt++) {
        if (kt + 1 < KT) asm volatile("cp.async.wait_group 1;" ::: "memory");
        else             asm volatile("cp.async.wait_group 0;" ::: "memory");
        __syncthreads();

        if (kt + 2 < KT) {
            int ns = stage + 2; if (ns >= 3) ns -= 3;
            load_tile(kt + 2, ns);
        }

        uint32_t ab  = sb + (uint32_t)(stage * STG) * 2;
        uint32_t bb0 = ab + A_T * 2;
        uint32_t bb1 = ab + (A_T + B_T) * 2;

#pragma unroll
        for (int ksid = 0; ksid < 4; ksid++) {
            const int ks = ksid * 16;
            uint32_t af[4][4];
#pragma unroll
            for (int mi = 0; mi < 4; mi++)
                ldsm4(af[mi][0], af[mi][1], af[mi][2], af[mi][3],
                      ab + (uint32_t)(aoff[mi] + ks) * 2);
            uint32_t bf0[2][2], bf1[2][2];
            ldsm4(bf0[0][0], bf0[0][1], bf0[1][0], bf0[1][1],
                  bb0 + (uint32_t)(boff + ks) * 2);
            ldsm4(bf1[0][0], bf1[0][1], bf1[1][0], bf1[1][1],
                  bb1 + (uint32_t)(boff + ks) * 2);
#pragma unroll
            for (int mi = 0; mi < 4; mi++)
#pragma unroll
                for (int ni = 0; ni < 2; ni++) {
                    mma16816(acc0[mi][ni], af[mi], bf0[ni]);
                    mma16816(acc1[mi][ni], af[mi], bf1[ni]);
                }
        }
        stage++; if (stage >= 3) stage = 0;
    }

    // epilogue
    const float s0 = g_scales[sbase];
    const float s1 = (EPI == 0) ? g_scales[sbase + 1] : s0;
    const int grp = lane >> 2, tig = lane & 3;

    if constexpr (EPI == 0) {
        const bool edge = ((nt + 1) * 64 > (unsigned)Nvalid);
#pragma unroll
        for (int mi = 0; mi < 4; mi++) {
#pragma unroll
            for (int ni = 0; ni < 2; ni++) {
                int rbase = mt * 128 + m0 + mi * 16 + grp;
                int cb    = nt * 64 + n0 + ni * 8 + tig * 2;
#pragma unroll
                for (int he = 0; he < 2; he++) {
                    int r = rbase + he * 8;
                    float g = acc0[mi][ni][he * 2 + 0] * s0;
                    float u = acc1[mi][ni][he * 2 + 0] * s1;
                    float h0 = u * (g / (1.f + __expf(-g)));
                    g = acc0[mi][ni][he * 2 + 1] * s0;
                    u = acc1[mi][ni][he * 2 + 1] * s1;
                    float h1 = u * (g / (1.f + __expf(-g)));
                    if (!edge || cb < Nvalid)
                        *(__half2*)(Ch + (size_t)r * ldc + cb) =
                            __floats2half2_rn(h0, h1);
                }
            }
        }
    } else {
#pragma unroll
        for (int mi = 0; mi < 4; mi++) {
#pragma unroll
            for (int ni = 0; ni < 2; ni++) {
                int rbase = mt * 128 + m0 + mi * 16 + grp;
                int cb0   = nt * 128 + n0 + ni * 8 + tig * 2;
#pragma unroll
                for (int he = 0; he < 2; he++) {
                    int r = rbase + he * 8;
                    float2 v0, v1;
                    v0.x = acc0[mi][ni][he * 2 + 0] * s0;
                    v0.y = acc0[mi][ni][he * 2 + 1] * s0;
                    v1.x = acc1[mi][ni][he * 2 + 0] * s0;
                    v1.y = acc1[mi][ni][he * 2 + 1] * s0;
                    *(float2*)(Cf + (size_t)r * ldc + cb0)      = v0;
                    *(float2*)(Cf + (size_t)r * ldc + cb0 + 64) = v1;
                }
            }
        }
    }
}

// ---------------------------------------------------------------------------
// launcher
// ---------------------------------------------------------------------------
extern "C" void kernel_launch(void* const* d_in, const int* in_sizes, int n_in,
                              void* d_out, int out_size) {
    (void)in_sizes; (void)n_in; (void)out_size;
    const float* x  = (const float*)d_in[0];
    const float* wg = (const float*)d_in[1];
    const float* wu = (const float*)d_in[2];
    const float* wd = (const float*)d_in[3];
    float* out = (float*)d_out;

    void* p;
    cudaGetSymbolAddress(&p, g_Mg); __half* Mg = (__half*)p;
    cudaGetSymbolAddress(&p, g_Mu); __half* Mu = (__half*)p;
    cudaGetSymbolAddress(&p, g_Md); __half* Md = (__half*)p;
    cudaGetSymbolAddress(&p, g_X);  __half* X  = (__half*)p;
    cudaGetSymbolAddress(&p, g_H);  __half* Hb = (__half*)p;

    reduce_abs_kernel<<<dim3(256, 3), 256>>>(wg, wu, wd, WN);
    finalize_scales_kernel<<<1, 256>>>(WN);

    int total_items = 2 * GU_ITEMS + D_ITEMS + X_ITEMS;
    build_all_kernel<<<(total_items + 255) / 256, 256>>>(
        Mg, Mu, Md, X, wg, wu, wd, x);

    constexpr int SMEM = 3 * (128 * 72 + 2 * 64 * 72) * (int)sizeof(__half); // 110592
    cudaFuncSetAttribute((const void*)hgemm<0>,
                         cudaFuncAttributeMaxDynamicSharedMemorySize, SMEM);
    cudaFuncSetAttribute((const void*)hgemm<1>,
                         cudaFuncAttributeMaxDynamicSharedMemorySize, SMEM);

    // fused gate+up -> H (fp16); grid: x = M tiles (fast), y = N strips
    hgemm<0><<<dim3(MROWS / 128, NH_PAD / 64), 256, SMEM>>>(
        X, KD, Mg, KD, Hb, nullptr, K2, NH, KD / 64, 0, Mu);

    // down -> out (fp32); grid: x = M tiles (fast), y = N strips
    hgemm<1><<<dim3(MROWS / 128, 4096 / 128), 256, SMEM>>>(
        Hb, K2, Md, K2, nullptr, out, 4096, 4096, K2 / 64, 2, nullptr);
}

// round 10
// speedup vs baseline: 1.7178x; 1.0146x over previous
#include <cuda_runtime.h>
#include <cuda_fp16.h>
#include <cstdint>
#include <cstddef>

// ---------------------------------------------------------------------------
// out = silu(x@Mg^T)*(x@Mu^T) @ Md^T, ternary-dequant octonion weights.
// Octonion structure collapses to j = i XOR k + sign LUT.
// R10: per-CTA K-loop phase rotation (kt0 = bid*37 mod KT) to desync the two
//      co-resident CTAs so MMA phases cover LDSM bursts + barrier drains.
// ---------------------------------------------------------------------------

static constexpr int MROWS = 4096, KD = 4096, NH = 10928, NH_PAD = 11008, K2 = 10944;
static constexpr int WN = 8 * 1366 * 512;

__device__ __half g_Mg[(size_t)NH_PAD * KD];
__device__ __half g_Mu[(size_t)NH_PAD * KD];
__device__ __half g_Md[(size_t)4096 * K2];
__device__ __half g_X [(size_t)MROWS * KD];
__device__ __half g_H [(size_t)MROWS * K2];
__device__ float  g_red[3 * 256];
__device__ float  g_scales[3];
__device__ float  g_inv[3];

// sign LUT: s[i*8+k] = S[i^k, i, k]
__constant__ float c_S[64] = {
 +1,+1,+1,+1,+1,+1,+1,+1,
 -1,+1,+1,-1,+1,-1,-1,+1,
 -1,-1,+1,+1,+1,+1,-1,-1,
 -1,+1,-1,+1,+1,-1,+1,-1,
 -1,-1,-1,-1,+1,+1,+1,+1,
 -1,+1,-1,+1,-1,+1,-1,+1,
 -1,+1,+1,-1,-1,+1,+1,-1,
 -1,-1,+1,+1,-1,-1,+1,+1};

// ---------------------------------------------------------------------------
// scales
// ---------------------------------------------------------------------------
__global__ void reduce_abs_kernel(const float* __restrict__ w0,
                                  const float* __restrict__ w1,
                                  const float* __restrict__ w2, int n) {
    int t = blockIdx.y;
    const float* w = (t == 0) ? w0 : (t == 1 ? w1 : w2);
    float s = 0.f;
    for (int i = blockIdx.x * blockDim.x + threadIdx.x; i < n;
         i += gridDim.x * blockDim.x)
        s += fabsf(w[i]);
    __shared__ float sh[256];
    sh[threadIdx.x] = s;
    __syncthreads();
    for (int st = 128; st > 0; st >>= 1) {
        if (threadIdx.x < st) sh[threadIdx.x] += sh[threadIdx.x + st];
        __syncthreads();
    }
    if (threadIdx.x == 0) g_red[t * 256 + blockIdx.x] = sh[0];
}

__global__ void finalize_scales_kernel(int n) {
    __shared__ float sh[256];
    for (int t = 0; t < 3; t++) {
        sh[threadIdx.x] = g_red[t * 256 + threadIdx.x];
        __syncthreads();
        for (int st = 128; st > 0; st >>= 1) {
            if (threadIdx.x < st) sh[threadIdx.x] += sh[threadIdx.x + st];
            __syncthreads();
        }
        if (threadIdx.x == 0) {
            float sc = sh[0] / (float)n;
            g_scales[t] = sc;
            g_inv[t]    = 1.0f / sc;
        }
        __syncthreads();
    }
}

// ---------------------------------------------------------------------------
// merged build: Mg, Mu, Md + x -> fp16
// ---------------------------------------------------------------------------
static constexpr int GU_ITEMS = NH * 512;
static constexpr int D_ITEMS  = 4096 * (K2 / 8);
static constexpr int X_ITEMS  = MROWS * KD / 8;

__global__ void build_all_kernel(__half* __restrict__ Mg, __half* __restrict__ Mu,
                                 __half* __restrict__ Md, __half* __restrict__ X,
                                 const float* __restrict__ wg,
                                 const float* __restrict__ wu,
                                 const float* __restrict__ wd,
                                 const float* __restrict__ x) {
    int id = blockIdx.x * blockDim.x + threadIdx.x;
    if (id < 2 * GU_ITEMS) {
        const float* W = (id < GU_ITEMS) ? wg : wu;
        __half* out    = (id < GU_ITEMS) ? Mg : Mu;
        float inv      = (id < GU_ITEMS) ? g_inv[0] : g_inv[1];
        int t  = (id < GU_ITEMS) ? id : id - GU_ITEMS;
        int r  = t >> 9;
        int c  = (t & 511) * 8;
        int k = r / 1366, o = r - k * 1366;
        int i = c >> 9, d = c & 511;
        int j = i ^ k;
        float sg = c_S[i * 8 + k];
        const float4* src = (const float4*)(W + ((size_t)(j * 1366 + o)) * 512 + d);
        float4 v0 = src[0], v1 = src[1];
        float q[8] = {v0.x, v0.y, v0.z, v0.w, v1.x, v1.y, v1.z, v1.w};
        __align__(16) __half h[8];
#pragma unroll
        for (int tt = 0; tt < 8; tt++) {
            float qq = rintf(q[tt] * inv);
            qq = fminf(1.f, fmaxf(-1.f, qq)) * sg;
            h[tt] = __float2half_rn(qq);
        }
        *(uint4*)(out + (size_t)r * 4096 + c) = *(uint4*)h;
        return;
    }
    int t = id - 2 * GU_ITEMS;
    if (t < D_ITEMS) {
        int r = t / (K2 / 8);
        int c = (t - r * (K2 / 8)) * 8;
        int k = r >> 9, o = r & 511;
        float inv = g_inv[2];
        int i = c / 1366, d = c - i * 1366;
        __align__(16) __half h[8];
#pragma unroll
        for (int tt = 0; tt < 8; tt++) {
            int cc = c + tt;
            if (cc < NH) {
                int j = i ^ k;
                float sg = c_S[i * 8 + k];
                float q = rintf(wd[((size_t)(j * 512 + o)) * 1366 + d] * inv);
                h[tt] = __float2half_rn(fminf(1.f, fmaxf(-1.f, q)) * sg);
            } else {
                h[tt] = __float2half_rn(0.f);
            }
            if (++d == 1366) { d = 0; ++i; }
        }
        *(uint4*)(Md + (size_t)r * K2 + c) = *(uint4*)h;
        return;
    }
    t -= D_ITEMS;
    if (t >= X_ITEMS) return;
    const float4* src = (const float4*)(x + (size_t)t * 8);
    float4 v0 = src[0], v1 = src[1];
    __align__(16) __half h[8];
    *(__half2*)(h + 0) = __floats2half2_rn(v0.x, v0.y);
    *(__half2*)(h + 2) = __floats2half2_rn(v0.z, v0.w);
    *(__half2*)(h + 4) = __floats2half2_rn(v1.x, v1.y);
    *(__half2*)(h + 6) = __floats2half2_rn(v1.z, v1.w);
    *(uint4*)(X + (size_t)t * 8) = *(uint4*)h;
}

// ---------------------------------------------------------------------------
// GEMM helpers
// ---------------------------------------------------------------------------
__device__ __forceinline__ uint32_t smem_u32(const void* p) {
    return (uint32_t)__cvta_generic_to_shared(p);
}
__device__ __forceinline__ void cp16(uint32_t s, const void* g) {
    asm volatile("cp.async.cg.shared.global [%0], [%1], 16;\n" :: "r"(s), "l"(g));
}
__device__ __forceinline__ void ldsm4(uint32_t& r0, uint32_t& r1, uint32_t& r2,
                                      uint32_t& r3, uint32_t addr) {
    asm volatile("ldmatrix.sync.aligned.m8n8.x4.shared.b16 {%0,%1,%2,%3}, [%4];"
                 : "=r"(r0), "=r"(r1), "=r"(r2), "=r"(r3) : "r"(addr));
}
__device__ __forceinline__ void mma16816(float c[4], const uint32_t a[4],
                                         const uint32_t b[2]) {
    asm("mma.sync.aligned.m16n8k16.row.col.f32.f16.f16.f32 "
        "{%0,%1,%2,%3}, {%4,%5,%6,%7}, {%8,%9}, {%0,%1,%2,%3};\n"
        : "+f"(c[0]), "+f"(c[1]), "+f"(c[2]), "+f"(c[3])
        : "r"(a[0]), "r"(a[1]), "r"(a[2]), "r"(a[3]), "r"(b[0]), "r"(b[1]));
}

// ---------------------------------------------------------------------------
// Dual-B HMMA GEMM, occupancy-2, transposed grid, K-phase rotated per CTA.
// EPI=0: B0=gate strip, B1=up strip -> silu(g)*u -> fp16 H (64 cols/CTA)
// EPI=1: B0,B1 = adjacent 64-row strips of Md -> fp32 out (128 cols/CTA)
// ---------------------------------------------------------------------------
template <int EPI>
__global__ void __launch_bounds__(256, 2)
hgemm(const __half* __restrict__ A, int lda,
      const __half* __restrict__ Bbase, int ldb,
      __half* __restrict__ Ch, float* __restrict__ Cf, int ldc,
      int Nvalid, int KT, int sbase,
      const __half* __restrict__ B1base) {
    extern __shared__ __align__(16) __half sm[];
    constexpr int LDA = 72;
    constexpr int A_T = 128 * LDA;
    constexpr int B_T = 64 * LDA;
    constexpr int STG = A_T + 2 * B_T;

    const int tid  = threadIdx.x;
    const int warp = tid >> 5, lane = tid & 31;
    const int wm = warp >> 2, wn = warp & 3;
    const int m0 = wm * 64, n0 = wn * 16;

    const int mt = blockIdx.x;          // M tile (fast)
    const int nt = blockIdx.y;          // N strip (slow)

    // K-phase rotation: desync co-resident CTAs (pure reordering of the
    // K-sum; deterministic per bid).
    const int bid = mt + nt * gridDim.x;
    const int kt0 = (bid * 37) % KT;

    const __half* Ag = A + (size_t)mt * 128 * lda;
    const __half* Bg0;
    const __half* Bg1;
    if (EPI == 0) {
        Bg0 = Bbase  + (size_t)nt * 64 * ldb;
        Bg1 = B1base + (size_t)nt * 64 * ldb;
    } else {
        Bg0 = Bbase + (size_t)nt * 128 * ldb;
        Bg1 = Bg0 + (size_t)64 * ldb;
    }

    int a_row = m0 + (lane & 7) + ((lane >> 3) & 1) * 8;
    int a_col = (lane >> 4) * 8;
    int aoff[4];
#pragma unroll
    for (int mi = 0; mi < 4; mi++) aoff[mi] = (a_row + mi * 16) * LDA + a_col;
    int b_row = n0 + (lane & 7) + ((lane >> 4) & 1) * 8;
    int b_col = ((lane >> 3) & 1) * 8;
    const int boff = b_row * LDA + b_col;

    const uint32_t sb = smem_u32(sm);

    float acc0[4][2][4];
    float acc1[4][2][4];
#pragma unroll
    for (int a = 0; a < 4; a++)
#pragma unroll
        for (int b = 0; b < 2; b++)
#pragma unroll
            for (int e = 0; e < 4; e++) { acc0[a][b][e] = 0.f; acc1[a][b][e] = 0.f; }

    auto load_tile = [&](int kt_rot, int s) {
        uint32_t st = sb + (uint32_t)(s * STG) * 2;
        int k0 = kt_rot * 64;
#pragma unroll
        for (int u = 0; u < 4; u++) {
            int id = u * 256 + tid;
            int row = id >> 3, ch = id & 7;
            cp16(st + row * (LDA * 2) + ch * 16,
                 Ag + (size_t)row * lda + k0 + ch * 8);
        }
#pragma unroll
        for (int u = 0; u < 2; u++) {
            int id = u * 256 + tid;
            int row = id >> 3, ch = id & 7;
            cp16(st + A_T * 2 + row * (LDA * 2) + ch * 16,
                 Bg0 + (size_t)row * ldb + k0 + ch * 8);
        }
#pragma unroll
        for (int u = 0; u < 2; u++) {
            int id = u * 256 + tid;
            int row = id >> 3, ch = id & 7;
            cp16(st + (A_T + B_T) * 2 + row * (LDA * 2) + ch * 16,
                 Bg1 + (size_t)row * ldb + k0 + ch * 8);
        }
        asm volatile("cp.async.commit_group;" ::: "memory");
    };

    auto rot = [&](int kt) { int r = kt0 + kt; if (r >= KT) r -= KT; return r; };

    load_tile(rot(0), 0);
    load_tile(rot(1), 1);

    int stage = 0;
    for (int kt = 0; kt < KT; kt++) {
        if (kt + 1 < KT) asm volatile("cp.async.wait_group 1;" ::: "memory");
        else             asm volatile("cp.async.wait_group 0;" ::: "memory");
        __syncthreads();

        if (kt + 2 < KT) {
            int ns = stage + 2; if (ns >= 3) ns -= 3;
            load_tile(rot(kt + 2), ns);
        }

        uint32_t ab  = sb + (uint32_t)(stage * STG) * 2;
        uint32_t bb0 = ab + A_T * 2;
        uint32_t bb1 = ab + (A_T + B_T) * 2;

#pragma unroll
        for (int ksid = 0; ksid < 4; ksid++) {
            const int ks = ksid * 16;
            uint32_t af[4][4];
#pragma unroll
            for (int mi = 0; mi < 4; mi++)
                ldsm4(af[mi][0], af[mi][1], af[mi][2], af[mi][3],
                      ab + (uint32_t)(aoff[mi] + ks) * 2);
            uint32_t bf0[2][2], bf1[2][2];
            ldsm4(bf0[0][0], bf0[0][1], bf0[1][0], bf0[1][1],
                  bb0 + (uint32_t)(boff + ks) * 2);
            ldsm4(bf1[0][0], bf1[0][1], bf1[1][0], bf1[1][1],
                  bb1 + (uint32_t)(boff + ks) * 2);
#pragma unroll
            for (int mi = 0; mi < 4; mi++)
#pragma unroll
                for (int ni = 0; ni < 2; ni++) {
                    mma16816(acc0[mi][ni], af[mi], bf0[ni]);
                    mma16816(acc1[mi][ni], af[mi], bf1[ni]);
                }
        }
        stage++; if (stage >= 3) stage = 0;
    }

    // epilogue
    const float s0 = g_scales[sbase];
    const float s1 = (EPI == 0) ? g_scales[sbase + 1] : s0;
    const int grp = lane >> 2, tig = lane & 3;

    if constexpr (EPI == 0) {
        const bool edge = ((nt + 1) * 64 > (unsigned)Nvalid);
#pragma unroll
        for (int mi = 0; mi < 4; mi++) {
#pragma unroll
            for (int ni = 0; ni < 2; ni++) {
                int rbase = mt * 128 + m0 + mi * 16 + grp;
                int cb    = nt * 64 + n0 + ni * 8 + tig * 2;
#pragma unroll
                for (int he = 0; he < 2; he++) {
                    int r = rbase + he * 8;
                    float g = acc0[mi][ni][he * 2 + 0] * s0;
                    float u = acc1[mi][ni][he * 2 + 0] * s1;
                    float h0 = u * (g / (1.f + __expf(-g)));
                    g = acc0[mi][ni][he * 2 + 1] * s0;
                    u = acc1[mi][ni][he * 2 + 1] * s1;
                    float h1 = u * (g / (1.f + __expf(-g)));
                    if (!edge || cb < Nvalid)
                        *(__half2*)(Ch + (size_t)r * ldc + cb) =
                            __floats2half2_rn(h0, h1);
                }
            }
        }
    } else {
#pragma unroll
        for (int mi = 0; mi < 4; mi++) {
#pragma unroll
            for (int ni = 0; ni < 2; ni++) {
                int rbase = mt * 128 + m0 + mi * 16 + grp;
                int cb0   = nt * 128 + n0 + ni * 8 + tig * 2;
#pragma unroll
                for (int he = 0; he < 2; he++) {
                    int r = rbase + he * 8;
                    float2 v0, v1;
                    v0.x = acc0[mi][ni][he * 2 + 0] * s0;
                    v0.y = acc0[mi][ni][he * 2 + 1] * s0;
                    v1.x = acc1[mi][ni][he * 2 + 0] * s0;
                    v1.y = acc1[mi][ni][he * 2 + 1] * s0;
                    *(float2*)(Cf + (size_t)r * ldc + cb0)      = v0;
                    *(float2*)(Cf + (size_t)r * ldc + cb0 + 64) = v1;
                }
            }
        }
    }
}

// ---------------------------------------------------------------------------
// launcher
// ---------------------------------------------------------------------------
extern "C" void kernel_launch(void* const* d_in, const int* in_sizes, int n_in,
                              void* d_out, int out_size) {
    (void)in_sizes; (void)n_in; (void)out_size;
    const float* x  = (const float*)d_in[0];
    const float* wg = (const float*)d_in[1];
    const float* wu = (const float*)d_in[2];
    const float* wd = (const float*)d_in[3];
    float* out = (float*)d_out;

    void* p;
    cudaGetSymbolAddress(&p, g_Mg); __half* Mg = (__half*)p;
    cudaGetSymbolAddress(&p, g_Mu); __half* Mu = (__half*)p;
    cudaGetSymbolAddress(&p, g_Md); __half* Md = (__half*)p;
    cudaGetSymbolAddress(&p, g_X);  __half* X  = (__half*)p;
    cudaGetSymbolAddress(&p, g_H);  __half* Hb = (__half*)p;

    reduce_abs_kernel<<<dim3(256, 3), 256>>>(wg, wu, wd, WN);
    finalize_scales_kernel<<<1, 256>>>(WN);

    int total_items = 2 * GU_ITEMS + D_ITEMS + X_ITEMS;
    build_all_kernel<<<(total_items + 255) / 256, 256>>>(
        Mg, Mu, Md, X, wg, wu, wd, x);

    constexpr int SMEM = 3 * (128 * 72 + 2 * 64 * 72) * (int)sizeof(__half); // 110592
    cudaFuncSetAttribute((const void*)hgemm<0>,
                         cudaFuncAttributeMaxDynamicSharedMemorySize, SMEM);
    cudaFuncSetAttribute((const void*)hgemm<1>,
                         cudaFuncAttributeMaxDynamicSharedMemorySize, SMEM);

    // fused gate+up -> H (fp16); grid: x = M tiles (fast), y = N strips
    hgemm<0><<<dim3(MROWS / 128, NH_PAD / 64), 256, SMEM>>>(
        X, KD, Mg, KD, Hb, nullptr, K2, NH, KD / 64, 0, Mu);

    // down -> out (fp32); grid: x = M tiles (fast), y = N strips
    hgemm<1><<<dim3(MROWS / 128, 4096 / 128), 256, SMEM>>>(
        Hb, K2, Md, K2, nullptr, out, 4096, 4096, K2 / 64, 2, nullptr);
}